// round 11
// baseline (speedup 1.0000x reference)
#include <cuda_runtime.h>
#include <cuda_bf16.h>
#include <cstdint>

// ---------------------------------------------------------------------------
// ViT block. B=16, C=384, N=1024 (32x32), NH=8, HD=48, MID=384, HID=1536.
// fp32 I/O; activations as TWO bf16 planes (hi, lo), [c][n] layout.
// mma.sync m16n8k16 bf16; GEMMs 3-product hi/lo split; attention QK 3-product,
// PV single-bf16 (error diluted by proj+residual). cp.async 2-stage pipelines.
// GEMM: 128x128 CTA tile, 512 threads, 4x4 warp grid. QKV fused.
// ---------------------------------------------------------------------------

#define BB   16
#define CC   384
#define NN   1024
#define NHH  8
#define HDD  48
#define MIDD 384
#define HIDD 1536
#define QKVO (3 * MIDD)   // 1152

__device__ __nv_bfloat16 g_lnh [BB * CC   * NN], g_lnl [BB * CC   * NN];
__device__ __nv_bfloat16 g_qkvh[BB * QKVO * NN], g_qkvl[BB * QKVO * NN];
__device__ __nv_bfloat16 g_aoh [BB * MIDD * NN], g_aol [BB * MIDD * NN];
__device__ __nv_bfloat16 g_mh  [BB * HIDD * NN], g_ml  [BB * HIDD * NN];
__device__ float         g_y1  [BB * CC   * NN];
__device__ float         g_bqkv[QKVO];
#define WOFF_Q    0
#define WOFF_KV   147456
#define WOFF_PROJ 442368
#define WOFF_W1   589824
#define WOFF_W2   1179648
#define WTOTAL    1769472
__device__ __nv_bfloat16 g_wh[WTOTAL], g_wl[WTOTAL];

__device__ __forceinline__ uint32_t smem_to_u32(const void* p) {
    uint32_t a;
    asm("{ .reg .u64 t; cvta.to.shared.u64 t, %1; cvt.u32.u64 %0, t; }" : "=r"(a) : "l"(p));
    return a;
}
__device__ __forceinline__ void ldmx4(uint32_t* r, uint32_t addr) {
    asm volatile("ldmatrix.sync.aligned.m8n8.x4.shared.b16 {%0,%1,%2,%3}, [%4];"
                 : "=r"(r[0]), "=r"(r[1]), "=r"(r[2]), "=r"(r[3]) : "r"(addr));
}
__device__ __forceinline__ void ldmx4t(uint32_t* r, uint32_t addr) {
    asm volatile("ldmatrix.sync.aligned.m8n8.x4.trans.shared.b16 {%0,%1,%2,%3}, [%4];"
                 : "=r"(r[0]), "=r"(r[1]), "=r"(r[2]), "=r"(r[3]) : "r"(addr));
}
__device__ __forceinline__ void mma16816(float* c, const uint32_t* a,
                                         uint32_t b0, uint32_t b1) {
    asm volatile("mma.sync.aligned.m16n8k16.row.col.f32.bf16.bf16.f32 "
                 "{%0,%1,%2,%3}, {%4,%5,%6,%7}, {%8,%9}, {%0,%1,%2,%3};"
                 : "+f"(c[0]), "+f"(c[1]), "+f"(c[2]), "+f"(c[3])
                 : "r"(a[0]), "r"(a[1]), "r"(a[2]), "r"(a[3]), "r"(b0), "r"(b1));
}
#define CP16(dst, src) \
    asm volatile("cp.async.cg.shared.global [%0], [%1], 16;" :: "r"(dst), "l"(src))
#define CP_COMMIT() asm volatile("cp.async.commit_group;" ::: "memory")
#define CP_WAIT1()  asm volatile("cp.async.wait_group 1;" ::: "memory")

// ---------------------------------------------------------------------------
__global__ __launch_bounds__(256)
void prep_kernel(const float* __restrict__ wq, const float* __restrict__ wkv,
                 const float* __restrict__ wproj, const float* __restrict__ w1,
                 const float* __restrict__ w2,
                 const float* __restrict__ bq, const float* __restrict__ bkv,
                 __nv_bfloat16* __restrict__ wh, __nv_bfloat16* __restrict__ wl,
                 float* __restrict__ bqkv)
{
    const int i = blockIdx.x * 256 + threadIdx.x;
    if (i < WTOTAL) {
        const float* src; int off;
        if      (i < WOFF_KV)   { src = wq;    off = i; }
        else if (i < WOFF_PROJ) { src = wkv;   off = i - WOFF_KV; }
        else if (i < WOFF_W1)   { src = wproj; off = i - WOFF_PROJ; }
        else if (i < WOFF_W2)   { src = w1;    off = i - WOFF_W1; }
        else                    { src = w2;    off = i - WOFF_W2; }
        const float v = src[off];
        const __nv_bfloat16 h = __float2bfloat16(v);
        wh[i] = h;
        wl[i] = __float2bfloat16(v - __bfloat162float(h));
    }
    if (i < QKVO) bqkv[i] = (i < MIDD) ? bq[i] : bkv[i - MIDD];
}

__global__ __launch_bounds__(256)
void ln_kernel(const float* __restrict__ x, const float* __restrict__ g,
               const float* __restrict__ beta,
               __nv_bfloat16* __restrict__ oh, __nv_bfloat16* __restrict__ ol)
{
    const int b = blockIdx.y;
    const int n = blockIdx.x * 256 + threadIdx.x;
    const float* xp = x + (size_t)b * CC * NN + n;

    float sum = 0.f, sq = 0.f;
    #pragma unroll 4
    for (int c = 0; c < CC; c++) {
        float v = xp[(size_t)c * NN];
        sum += v; sq += v * v;
    }
    const float mean = sum * (1.f / CC);
    float var = sq * (1.f / CC) - mean * mean;
    var = var < 0.f ? 0.f : var;
    const float rstd = rsqrtf(var + 1e-5f);

    __nv_bfloat16* ph = oh + (size_t)b * CC * NN + n;
    __nv_bfloat16* pl = ol + (size_t)b * CC * NN + n;
    #pragma unroll 4
    for (int c = 0; c < CC; c++) {
        float v = (xp[(size_t)c * NN] - mean) * rstd * g[c] + beta[c];
        const __nv_bfloat16 h = __float2bfloat16(v);
        ph[(size_t)c * NN] = h;
        pl[(size_t)c * NN] = __float2bfloat16(v - __bfloat162float(h));
    }
}

// ---------------------------------------------------------------------------
// Pipelined HMMA GEMM, CTA 128(m) x 128(o), 512 threads = 16 warps (4m x 4n).
// A: K-major smem [64 k][136h] (272B rows, trans frags) — 1024 16B chunks.
// B: o-major smem [128 o][72h] (144B rows, non-trans frags) — 1024 chunks.
// EPI: 1 = fp32 + residual; 3 = hi/lo planes; 4 = GELU + planes.
// ---------------------------------------------------------------------------
#define GROW 272
#define BROW 144
#define ST_A_HI 0
#define ST_A_LO 17408
#define ST_B_HI 34816
#define ST_B_LO 53248
#define ST_SIZE 71680
#define SM_GEMM_TOTAL (2 * ST_SIZE)   // 143360

template<int EPI>
__global__ __launch_bounds__(512, 1)
void mma_gemm(const __nv_bfloat16* __restrict__ Wh, const __nv_bfloat16* __restrict__ Wl,
              const __nv_bfloat16* __restrict__ Ah, const __nv_bfloat16* __restrict__ Al,
              const float* __restrict__ bias, const float* __restrict__ res,
              void* __restrict__ out1, void* __restrict__ out2, int O, int K)
{
    extern __shared__ __align__(16) char smem[];
    const uint32_t sbase = smem_to_u32(smem);

    const int b   = blockIdx.z;
    const int n0  = blockIdx.x * 128;
    const int o0  = blockIdx.y * 128;
    const int tid = threadIdx.x;
    const int wid = tid >> 5;
    const int lane = tid & 31;
    const int wm = wid & 3;     // 4 m-warps (32 tokens each)
    const int wn = wid >> 2;    // 4 n-warps (32 o each)

    const __nv_bfloat16* Abh = Ah + (size_t)b * K * NN;
    const __nv_bfloat16* Abl = Al + (size_t)b * K * NN;

    float acc[2][4][4];
    #pragma unroll
    for (int i = 0; i < 2; i++)
        #pragma unroll
        for (int j = 0; j < 4; j++)
            #pragma unroll
            for (int e = 0; e < 4; e++) acc[i][j][e] = 0.f;

    const int a_kr = (lane & 7) + ((lane & 16) ? 8 : 0);
    const int a_mc = ((lane & 8) ? 8 : 0);
    const int b_row = wn * 32 + (lane & 7) + ((lane >> 4) & 1) * 8;
    const int b_kg  = (lane >> 3) & 1;

    const int nchunks = K >> 6;

    auto prefetch = [&](int chunk, int stage) {
        const uint32_t sbuf = sbase + stage * ST_SIZE;
        const int k0 = chunk << 6;
        // A: [64 k][128 n] = 1024 chunks of 16B per plane, 2 per thread
        #pragma unroll
        for (int r = 0; r < 2; r++) {
            const int u = tid + 512 * r;
            const int row = u >> 4, blk = u & 15;
            const uint32_t d = (uint32_t)(row * GROW + blk * 16);
            const size_t aidx = (size_t)(k0 + row) * NN + n0 + blk * 8;
            CP16(sbuf + ST_A_HI + d, Abh + aidx);
            CP16(sbuf + ST_A_LO + d, Abl + aidx);
        }
        // B: [128 o][64 k] = 1024 chunks of 16B per plane, 2 per thread
        #pragma unroll
        for (int r = 0; r < 2; r++) {
            const int u = tid + 512 * r;
            const int row = u >> 3, g = u & 7;
            const uint32_t d = (uint32_t)(row * BROW + g * 16);
            const size_t widx = (size_t)(o0 + row) * K + k0 + g * 8;
            CP16(sbuf + ST_B_HI + d, Wh + widx);
            CP16(sbuf + ST_B_LO + d, Wl + widx);
        }
    };

    prefetch(0, 0); CP_COMMIT();

    for (int chunk = 0; chunk < nchunks; chunk++) {
        const int cur = chunk & 1;
        if (chunk + 1 < nchunks) prefetch(chunk + 1, cur ^ 1);
        CP_COMMIT();
        CP_WAIT1();
        __syncthreads();

        const uint32_t sbuf = sbase + cur * ST_SIZE;
        #pragma unroll
        for (int ks = 0; ks < 4; ks++) {
            uint32_t bh[8], bl[8];
            #pragma unroll
            for (int ng = 0; ng < 2; ng++) {
                const uint32_t boff =
                    (uint32_t)((b_row + ng * 16) * BROW + (ks * 2 + b_kg) * 16);
                ldmx4(&bh[ng * 4], sbuf + ST_B_HI + boff);
                ldmx4(&bl[ng * 4], sbuf + ST_B_LO + boff);
            }
            #pragma unroll
            for (int mf = 0; mf < 2; mf++) {
                const uint32_t aoff = (uint32_t)((ks * 16 + a_kr) * GROW
                                   + (wm * 32 + mf * 16 + a_mc) * 2);
                uint32_t ah[4], al[4];
                ldmx4t(ah, sbuf + ST_A_HI + aoff);
                ldmx4t(al, sbuf + ST_A_LO + aoff);
                #pragma unroll
                for (int nf = 0; nf < 4; nf++) {
                    const int bi = (nf >> 1) * 4 + (nf & 1) * 2;
                    mma16816(acc[mf][nf], ah, bh[bi], bh[bi + 1]);
                    mma16816(acc[mf][nf], ah, bl[bi], bl[bi + 1]);
                    mma16816(acc[mf][nf], al, bh[bi], bh[bi + 1]);
                }
            }
        }
        __syncthreads();
    }

    // Epilogue: transpose via smem [128 o][132 m], coalesced writes
    float* Cs = (float*)smem;
    #pragma unroll
    for (int mf = 0; mf < 2; mf++) {
        const int m = wm * 32 + mf * 16 + (lane >> 2);
        #pragma unroll
        for (int nf = 0; nf < 4; nf++) {
            const int ol = wn * 32 + nf * 8 + (lane & 3) * 2;
            Cs[ ol      * 132 + m    ] = acc[mf][nf][0];
            Cs[(ol + 1) * 132 + m    ] = acc[mf][nf][1];
            Cs[ ol      * 132 + m + 8] = acc[mf][nf][2];
            Cs[(ol + 1) * 132 + m + 8] = acc[mf][nf][3];
        }
    }
    __syncthreads();

    #pragma unroll 4
    for (int i = 0; i < 32; i++) {
        const int idx = tid + 512 * i;
        const int ol = idx >> 7;
        const int m  = idx & 127;
        const int o  = o0 + ol;
        float v = Cs[ol * 132 + m] + bias[o];
        const size_t gidx = ((size_t)b * O + o) * NN + n0 + m;
        if (EPI == 1) {
            ((float*)out1)[gidx] = v + res[gidx];
        } else {
            if (EPI == 4) v = 0.5f * v * (1.f + erff(v * 0.7071067811865476f));
            const __nv_bfloat16 h = __float2bfloat16(v);
            ((__nv_bfloat16*)out1)[gidx] = h;
            ((__nv_bfloat16*)out2)[gidx] = __float2bfloat16(v - __bfloat162float(h));
        }
    }
}

// ---------------------------------------------------------------------------
// Pipelined MMA flash attention. QK: 3-product split. PV: single bf16
// (P hi only, V hi plane only — error diluted by proj + residual).
// ---------------------------------------------------------------------------
#define AST_KHI 0
#define AST_KLO 13056
#define AST_VHI 26112
#define AST_SIZE 39168
#define AT_BIAS_OFF 78336
#define AT_SMEM_TOTAL (78336 + 35 * 64 * 4)   // 87296
#define ATT_SCALE 0.14433756729740643f

__global__ __launch_bounds__(256, 1)
void attn_kernel(const __nv_bfloat16* __restrict__ QKVh,
                 const __nv_bfloat16* __restrict__ QKVl,
                 const float* __restrict__ rpb,
                 __nv_bfloat16* __restrict__ Oh, __nv_bfloat16* __restrict__ Ol)
{
    extern __shared__ __align__(16) char smem[];
    const uint32_t sb = smem_to_u32(smem);
    const int tid = threadIdx.x, lane = tid & 31, w = tid >> 5;
    const int qb = blockIdx.x, h = blockIdx.y, b = blockIdx.z;

    float* bias_s = (float*)(smem + AT_BIAS_OFF);
    for (int e = tid; e < 35 * 63; e += 256) {
        const int a = e / 63, dw = e % 63;
        bias_s[a * 64 + dw] = rpb[((size_t)((a + qb * 4) * 63 + dw)) * NHH + h];
    }

    const size_t qrow = (size_t)(b * QKVO + h * HDD) * NN;
    const size_t krow = (size_t)(b * QKVO + MIDD + h * HDD) * NN;
    const size_t vrow = (size_t)(b * QKVO + 2 * MIDD + h * HDD) * NN;

    auto prefetchKV = [&](int kb, int stage) {
        const uint32_t sbuf = sb + stage * AST_SIZE;
        #pragma unroll
        for (int r = 0; r < 3; r++) {
            const int u = tid + 256 * r;
            const int row = u >> 4, blk = u & 15;
            const uint32_t d = (uint32_t)(row * GROW + blk * 16);
            const size_t kidx = krow + (size_t)row * NN + kb * 128 + blk * 8;
            const size_t vidx = vrow + (size_t)row * NN + kb * 128 + blk * 8;
            CP16(sbuf + AST_KHI + d, QKVh + kidx);
            CP16(sbuf + AST_KLO + d, QKVl + kidx);
            CP16(sbuf + AST_VHI + d, QKVh + vidx);
        }
    };

    {   // stage Q into stage-1 K planes
        const uint32_t sbuf = sb + AST_SIZE;
        #pragma unroll
        for (int r = 0; r < 3; r++) {
            const int u = tid + 256 * r;
            const int row = u >> 4, blk = u & 15;
            const uint32_t d = (uint32_t)(row * GROW + blk * 16);
            const size_t qidx = qrow + (size_t)row * NN + qb * 128 + blk * 8;
            CP16(sbuf + AST_KHI + d, QKVh + qidx);
            CP16(sbuf + AST_KLO + d, QKVl + qidx);
        }
    }
    CP_COMMIT();
    prefetchKV(0, 0); CP_COMMIT();
    CP_WAIT1();
    __syncthreads();

    uint32_t qfh[3][4], qfl[3][4];
    {
        const int q_dr = (lane & 7) + ((lane & 16) ? 8 : 0);
        const int q_mc = ((lane & 8) ? 8 : 0);
        #pragma unroll
        for (int ks = 0; ks < 3; ks++) {
            const uint32_t off = (uint32_t)((ks * 16 + q_dr) * GROW
                               + (w * 16 + q_mc) * 2);
            ldmx4t(qfh[ks], sb + AST_SIZE + AST_KHI + off);
            ldmx4t(qfl[ks], sb + AST_SIZE + AST_KLO + off);
        }
    }
    __syncthreads();

    float of[6][4];
    #pragma unroll
    for (int i = 0; i < 6; i++)
        #pragma unroll
        for (int e = 0; e < 4; e++) of[i][e] = 0.f;
    float mrow0 = -1e30f, mrow1 = -1e30f, lrow0 = 0.f, lrow1 = 0.f;

    const int trow0 = w * 16 + (lane >> 2);
    const int hn0 = trow0 >> 5, wn0 = trow0 & 31;
    const int trow1 = trow0 + 8;
    const int hn1 = trow1 >> 5, wn1 = trow1 & 31;

    const int b_dr = (lane & 7) + ((lane & 8) ? 8 : 0);
    const int b_kc = ((lane & 16) ? 8 : 0);
    const int v_dr = (lane & 7) + ((lane & 16) ? 8 : 0);
    const int v_kc = ((lane & 8) ? 8 : 0);

    for (int kb = 0; kb < 8; kb++) {
        const int cur = kb & 1;
        if (kb + 1 < 8) prefetchKV(kb + 1, cur ^ 1);
        CP_COMMIT();
        CP_WAIT1();
        __syncthreads();
        const uint32_t sbuf = sb + cur * AST_SIZE;

        float s[16][4];
        #pragma unroll
        for (int i = 0; i < 16; i++)
            #pragma unroll
            for (int e = 0; e < 4; e++) s[i][e] = 0.f;

        #pragma unroll
        for (int ks = 0; ks < 3; ks++) {
            #pragma unroll
            for (int np = 0; np < 8; np++) {
                const uint32_t off = (uint32_t)((ks * 16 + b_dr) * GROW
                                   + (np * 16 + b_kc) * 2);
                uint32_t kh4[4], kl4[4];
                ldmx4t(kh4, sbuf + AST_KHI + off);
                ldmx4t(kl4, sbuf + AST_KLO + off);
                mma16816(s[2*np],   qfh[ks], kh4[0], kh4[1]);
                mma16816(s[2*np],   qfh[ks], kl4[0], kl4[1]);
                mma16816(s[2*np],   qfl[ks], kh4[0], kh4[1]);
                mma16816(s[2*np+1], qfh[ks], kh4[2], kh4[3]);
                mma16816(s[2*np+1], qfh[ks], kl4[2], kl4[3]);
                mma16816(s[2*np+1], qfl[ks], kh4[2], kh4[3]);
            }
        }

        float mx0 = -1e30f, mx1 = -1e30f;
        #pragma unroll
        for (int nf = 0; nf < 16; nf++) {
            const int j0 = nf * 8 + (lane & 3) * 2;
            const int hm = kb * 4 + (j0 >> 5);
            const int wm = j0 & 31;
            const float* br0 = bias_s + (hn0 + 31 - hm) * 64 + (wn0 - wm + 31);
            const float* br1 = bias_s + (hn1 + 31 - hm) * 64 + (wn1 - wm + 31);
            s[nf][0] = s[nf][0] * ATT_SCALE + br0[0];
            s[nf][1] = s[nf][1] * ATT_SCALE + br0[-1];
            s[nf][2] = s[nf][2] * ATT_SCALE + br1[0];
            s[nf][3] = s[nf][3] * ATT_SCALE + br1[-1];
            mx0 = fmaxf(mx0, fmaxf(s[nf][0], s[nf][1]));
            mx1 = fmaxf(mx1, fmaxf(s[nf][2], s[nf][3]));
        }
        mx0 = fmaxf(mx0, __shfl_xor_sync(0xffffffffu, mx0, 1));
        mx0 = fmaxf(mx0, __shfl_xor_sync(0xffffffffu, mx0, 2));
        mx1 = fmaxf(mx1, __shfl_xor_sync(0xffffffffu, mx1, 1));
        mx1 = fmaxf(mx1, __shfl_xor_sync(0xffffffffu, mx1, 2));
        const float mn0 = fmaxf(mrow0, mx0), mn1 = fmaxf(mrow1, mx1);
        const float c0 = __expf(mrow0 - mn0), c1 = __expf(mrow1 - mn1);
        mrow0 = mn0; mrow1 = mn1;
        #pragma unroll
        for (int nf = 0; nf < 6; nf++) {
            of[nf][0] *= c0; of[nf][1] *= c0;
            of[nf][2] *= c1; of[nf][3] *= c1;
        }
        float sum0 = 0.f, sum1 = 0.f;
        #pragma unroll
        for (int nf = 0; nf < 16; nf++) {
            s[nf][0] = __expf(s[nf][0] - mn0); sum0 += s[nf][0];
            s[nf][1] = __expf(s[nf][1] - mn0); sum0 += s[nf][1];
            s[nf][2] = __expf(s[nf][2] - mn1); sum1 += s[nf][2];
            s[nf][3] = __expf(s[nf][3] - mn1); sum1 += s[nf][3];
        }
        sum0 += __shfl_xor_sync(0xffffffffu, sum0, 1);
        sum0 += __shfl_xor_sync(0xffffffffu, sum0, 2);
        sum1 += __shfl_xor_sync(0xffffffffu, sum1, 1);
        sum1 += __shfl_xor_sync(0xffffffffu, sum1, 2);
        lrow0 = lrow0 * c0 + sum0;
        lrow1 = lrow1 * c1 + sum1;

        // O += P V : P single bf16 (hi only), V hi plane only
        #pragma unroll
        for (int ks = 0; ks < 8; ks++) {
            uint32_t ah[4];
            {
                const float f[8] = {s[2*ks][0],   s[2*ks][1],   s[2*ks][2],   s[2*ks][3],
                                    s[2*ks+1][0], s[2*ks+1][1], s[2*ks+1][2], s[2*ks+1][3]};
                #pragma unroll
                for (int i = 0; i < 4; i++) {
                    __nv_bfloat162 hh(__float2bfloat16(f[2*i]), __float2bfloat16(f[2*i+1]));
                    ah[i] = *(uint32_t*)&hh;
                }
            }
            #pragma unroll
            for (int np = 0; np < 3; np++) {
                const uint32_t off = (uint32_t)((np * 16 + v_dr) * GROW
                                   + (ks * 16 + v_kc) * 2);
                uint32_t vh4[4];
                ldmx4(vh4, sbuf + AST_VHI + off);
                mma16816(of[2*np],   ah, vh4[0], vh4[1]);
                mma16816(of[2*np+1], ah, vh4[2], vh4[3]);
            }
        }
        __syncthreads();
    }

    const float inv0 = 1.f / lrow0, inv1 = 1.f / lrow1;
    float* Os = (float*)smem;   // [48 d][132]
    #pragma unroll
    for (int nf = 0; nf < 6; nf++) {
        const int d0 = nf * 8 + (lane & 3) * 2;
        const int t0 = w * 16 + (lane >> 2);
        Os[ d0      * 132 + t0    ] = of[nf][0] * inv0;
        Os[(d0 + 1) * 132 + t0    ] = of[nf][1] * inv0;
        Os[ d0      * 132 + t0 + 8] = of[nf][2] * inv1;
        Os[(d0 + 1) * 132 + t0 + 8] = of[nf][3] * inv1;
    }
    __syncthreads();
    const size_t orow = (size_t)(b * MIDD + h * HDD) * NN;
    #pragma unroll
    for (int i = 0; i < 24; i++) {
        const int u = tid + 256 * i;
        const int d = u >> 7, t = u & 127;
        const float v = Os[d * 132 + t];
        const size_t gidx = orow + (size_t)d * NN + qb * 128 + t;
        const __nv_bfloat16 hh = __float2bfloat16(v);
        Oh[gidx] = hh;
        Ol[gidx] = __float2bfloat16(v - __bfloat162float(hh));
    }
}

// ---------------------------------------------------------------------------
extern "C" void kernel_launch(void* const* d_in, const int* in_sizes, int n_in,
                              void* d_out, int out_size)
{
    const float* x     = (const float*)d_in[0];
    const float* rpb   = (const float*)d_in[1];
    const float* ln1_g = (const float*)d_in[3];
    const float* ln1_b = (const float*)d_in[4];
    const float* ln2_g = (const float*)d_in[5];
    const float* ln2_b = (const float*)d_in[6];
    const float* wq    = (const float*)d_in[7];
    const float* bq    = (const float*)d_in[8];
    const float* wkv   = (const float*)d_in[9];
    const float* bkv   = (const float*)d_in[10];
    const float* wproj = (const float*)d_in[11];
    const float* bproj = (const float*)d_in[12];
    const float* w1    = (const float*)d_in[13];
    const float* b1    = (const float*)d_in[14];
    const float* w2    = (const float*)d_in[15];
    const float* b2    = (const float*)d_in[16];
    float* out = (float*)d_out;

    __nv_bfloat16 *p_lnh, *p_lnl, *p_qkvh, *p_qkvl,
                  *p_aoh, *p_aol, *p_mh, *p_ml, *p_wh, *p_wl;
    float *p_y1, *p_bqkv;
    cudaGetSymbolAddress((void**)&p_lnh,  g_lnh);
    cudaGetSymbolAddress((void**)&p_lnl,  g_lnl);
    cudaGetSymbolAddress((void**)&p_qkvh, g_qkvh);
    cudaGetSymbolAddress((void**)&p_qkvl, g_qkvl);
    cudaGetSymbolAddress((void**)&p_aoh,  g_aoh);
    cudaGetSymbolAddress((void**)&p_aol,  g_aol);
    cudaGetSymbolAddress((void**)&p_mh,   g_mh);
    cudaGetSymbolAddress((void**)&p_ml,   g_ml);
    cudaGetSymbolAddress((void**)&p_y1,   g_y1);
    cudaGetSymbolAddress((void**)&p_wh,   g_wh);
    cudaGetSymbolAddress((void**)&p_wl,   g_wl);
    cudaGetSymbolAddress((void**)&p_bqkv, g_bqkv);

    cudaFuncSetAttribute(mma_gemm<1>, cudaFuncAttributeMaxDynamicSharedMemorySize, SM_GEMM_TOTAL);
    cudaFuncSetAttribute(mma_gemm<3>, cudaFuncAttributeMaxDynamicSharedMemorySize, SM_GEMM_TOTAL);
    cudaFuncSetAttribute(mma_gemm<4>, cudaFuncAttributeMaxDynamicSharedMemorySize, SM_GEMM_TOTAL);
    cudaFuncSetAttribute(attn_kernel, cudaFuncAttributeMaxDynamicSharedMemorySize, AT_SMEM_TOTAL);

    prep_kernel<<<(WTOTAL + 255) / 256, 256>>>(wq, wkv, wproj, w1, w2, bq, bkv,
                                               p_wh, p_wl, p_bqkv);

    const dim3 lnGrid(NN / 256, BB);

    ln_kernel<<<lnGrid, 256>>>(x, ln1_g, ln1_b, p_lnh, p_lnl);
    mma_gemm<3><<<dim3(NN/128, QKVO/128, BB), 512, SM_GEMM_TOTAL>>>(
        p_wh + WOFF_Q, p_wl + WOFF_Q, p_lnh, p_lnl, p_bqkv, nullptr,
        p_qkvh, p_qkvl, QKVO, CC);
    attn_kernel<<<dim3(NN/128, NHH, BB), 256, AT_SMEM_TOTAL>>>(
        p_qkvh, p_qkvl, rpb, p_aoh, p_aol);
    mma_gemm<1><<<dim3(NN/128, CC/128, BB), 512, SM_GEMM_TOTAL>>>(
        p_wh + WOFF_PROJ, p_wl + WOFF_PROJ, p_aoh, p_aol, bproj, x, p_y1, nullptr, CC, MIDD);
    ln_kernel<<<lnGrid, 256>>>(p_y1, ln2_g, ln2_b, p_lnh, p_lnl);
    mma_gemm<4><<<dim3(NN/128, HIDD/128, BB), 512, SM_GEMM_TOTAL>>>(
        p_wh + WOFF_W1, p_wl + WOFF_W1, p_lnh, p_lnl, b1, nullptr, p_mh, p_ml, HIDD, CC);
    mma_gemm<1><<<dim3(NN/128, CC/128, BB), 512, SM_GEMM_TOTAL>>>(
        p_wh + WOFF_W2, p_wl + WOFF_W2, p_mh, p_ml, b2, p_y1, out, nullptr, CC, HIDD);
}

// round 12
// speedup vs baseline: 1.0799x; 1.0799x over previous
#include <cuda_runtime.h>
#include <cuda_bf16.h>
#include <cstdint>

// ---------------------------------------------------------------------------
// ViT block. B=16, C=384, N=1024 (32x32), NH=8, HD=48, MID=384, HID=1536.
// fp32 I/O; activations as TWO bf16 planes (hi, lo), [c][n] layout.
// mma.sync m16n8k16 bf16; GEMMs 3-product hi/lo split; attention QK 3-product,
// PV single-bf16. cp.async 2-stage pipelines.
// GEMM: 128x64 CTA tile, 256 threads, 2 CTAs/SM (round-9 measured config).
// Attention: round-11 measured config (199.6 us). QKV fused.
// ---------------------------------------------------------------------------

#define BB   16
#define CC   384
#define NN   1024
#define NHH  8
#define HDD  48
#define MIDD 384
#define HIDD 1536
#define QKVO (3 * MIDD)   // 1152

__device__ __nv_bfloat16 g_lnh [BB * CC   * NN], g_lnl [BB * CC   * NN];
__device__ __nv_bfloat16 g_qkvh[BB * QKVO * NN], g_qkvl[BB * QKVO * NN];
__device__ __nv_bfloat16 g_aoh [BB * MIDD * NN], g_aol [BB * MIDD * NN];
__device__ __nv_bfloat16 g_mh  [BB * HIDD * NN], g_ml  [BB * HIDD * NN];
__device__ float         g_y1  [BB * CC   * NN];
__device__ float         g_bqkv[QKVO];
#define WOFF_Q    0
#define WOFF_KV   147456
#define WOFF_PROJ 442368
#define WOFF_W1   589824
#define WOFF_W2   1179648
#define WTOTAL    1769472
__device__ __nv_bfloat16 g_wh[WTOTAL], g_wl[WTOTAL];

__device__ __forceinline__ uint32_t smem_to_u32(const void* p) {
    uint32_t a;
    asm("{ .reg .u64 t; cvta.to.shared.u64 t, %1; cvt.u32.u64 %0, t; }" : "=r"(a) : "l"(p));
    return a;
}
__device__ __forceinline__ void ldmx4(uint32_t* r, uint32_t addr) {
    asm volatile("ldmatrix.sync.aligned.m8n8.x4.shared.b16 {%0,%1,%2,%3}, [%4];"
                 : "=r"(r[0]), "=r"(r[1]), "=r"(r[2]), "=r"(r[3]) : "r"(addr));
}
__device__ __forceinline__ void ldmx4t(uint32_t* r, uint32_t addr) {
    asm volatile("ldmatrix.sync.aligned.m8n8.x4.trans.shared.b16 {%0,%1,%2,%3}, [%4];"
                 : "=r"(r[0]), "=r"(r[1]), "=r"(r[2]), "=r"(r[3]) : "r"(addr));
}
__device__ __forceinline__ void mma16816(float* c, const uint32_t* a,
                                         uint32_t b0, uint32_t b1) {
    asm volatile("mma.sync.aligned.m16n8k16.row.col.f32.bf16.bf16.f32 "
                 "{%0,%1,%2,%3}, {%4,%5,%6,%7}, {%8,%9}, {%0,%1,%2,%3};"
                 : "+f"(c[0]), "+f"(c[1]), "+f"(c[2]), "+f"(c[3])
                 : "r"(a[0]), "r"(a[1]), "r"(a[2]), "r"(a[3]), "r"(b0), "r"(b1));
}
#define CP16(dst, src) \
    asm volatile("cp.async.cg.shared.global [%0], [%1], 16;" :: "r"(dst), "l"(src))
#define CP_COMMIT() asm volatile("cp.async.commit_group;" ::: "memory")
#define CP_WAIT1()  asm volatile("cp.async.wait_group 1;" ::: "memory")

// ---------------------------------------------------------------------------
__global__ __launch_bounds__(256)
void prep_kernel(const float* __restrict__ wq, const float* __restrict__ wkv,
                 const float* __restrict__ wproj, const float* __restrict__ w1,
                 const float* __restrict__ w2,
                 const float* __restrict__ bq, const float* __restrict__ bkv,
                 __nv_bfloat16* __restrict__ wh, __nv_bfloat16* __restrict__ wl,
                 float* __restrict__ bqkv)
{
    const int i = blockIdx.x * 256 + threadIdx.x;
    if (i < WTOTAL) {
        const float* src; int off;
        if      (i < WOFF_KV)   { src = wq;    off = i; }
        else if (i < WOFF_PROJ) { src = wkv;   off = i - WOFF_KV; }
        else if (i < WOFF_W1)   { src = wproj; off = i - WOFF_PROJ; }
        else if (i < WOFF_W2)   { src = w1;    off = i - WOFF_W1; }
        else                    { src = w2;    off = i - WOFF_W2; }
        const float v = src[off];
        const __nv_bfloat16 h = __float2bfloat16(v);
        wh[i] = h;
        wl[i] = __float2bfloat16(v - __bfloat162float(h));
    }
    if (i < QKVO) bqkv[i] = (i < MIDD) ? bq[i] : bkv[i - MIDD];
}

__global__ __launch_bounds__(256)
void ln_kernel(const float* __restrict__ x, const float* __restrict__ g,
               const float* __restrict__ beta,
               __nv_bfloat16* __restrict__ oh, __nv_bfloat16* __restrict__ ol)
{
    const int b = blockIdx.y;
    const int n = blockIdx.x * 256 + threadIdx.x;
    const float* xp = x + (size_t)b * CC * NN + n;

    float sum = 0.f, sq = 0.f;
    #pragma unroll 4
    for (int c = 0; c < CC; c++) {
        float v = xp[(size_t)c * NN];
        sum += v; sq += v * v;
    }
    const float mean = sum * (1.f / CC);
    float var = sq * (1.f / CC) - mean * mean;
    var = var < 0.f ? 0.f : var;
    const float rstd = rsqrtf(var + 1e-5f);

    __nv_bfloat16* ph = oh + (size_t)b * CC * NN + n;
    __nv_bfloat16* pl = ol + (size_t)b * CC * NN + n;
    #pragma unroll 4
    for (int c = 0; c < CC; c++) {
        float v = (xp[(size_t)c * NN] - mean) * rstd * g[c] + beta[c];
        const __nv_bfloat16 h = __float2bfloat16(v);
        ph[(size_t)c * NN] = h;
        pl[(size_t)c * NN] = __float2bfloat16(v - __bfloat162float(h));
    }
}

// ---------------------------------------------------------------------------
// Pipelined HMMA GEMM, CTA 128(m) x 64(o), 256 threads, 2 CTAs/SM (round 9).
// A: K-major smem [64 k][136h] (272B rows, trans frags).
// B: o-major smem [64 o][72h] (144B rows, non-trans frags).
// 8 warps = 4(m) x 2(n); warp tile 32x32.
// EPI: 1 = fp32 + residual; 3 = hi/lo planes; 4 = GELU + planes.
// ---------------------------------------------------------------------------
#define GROW 272
#define BROW 144
#define ST_A_HI 0
#define ST_A_LO 17408
#define ST_B_HI 34816
#define ST_B_LO 44032
#define ST_SIZE 53248
#define SM_GEMM_TOTAL (2 * ST_SIZE)   // 106496

template<int EPI>
__global__ __launch_bounds__(256, 2)
void mma_gemm(const __nv_bfloat16* __restrict__ Wh, const __nv_bfloat16* __restrict__ Wl,
              const __nv_bfloat16* __restrict__ Ah, const __nv_bfloat16* __restrict__ Al,
              const float* __restrict__ bias, const float* __restrict__ res,
              void* __restrict__ out1, void* __restrict__ out2, int O, int K)
{
    extern __shared__ __align__(16) char smem[];
    const uint32_t sbase = smem_to_u32(smem);

    const int b   = blockIdx.z;
    const int n0  = blockIdx.x * 128;
    const int o0  = blockIdx.y * 64;
    const int tid = threadIdx.x;
    const int wid = tid >> 5;
    const int lane = tid & 31;
    const int wm = wid & 3;     // 4 m-warps (32 tokens each)
    const int wn = wid >> 2;    // 2 n-warps (32 o each)

    const __nv_bfloat16* Abh = Ah + (size_t)b * K * NN;
    const __nv_bfloat16* Abl = Al + (size_t)b * K * NN;

    float acc[2][4][4];
    #pragma unroll
    for (int i = 0; i < 2; i++)
        #pragma unroll
        for (int j = 0; j < 4; j++)
            #pragma unroll
            for (int e = 0; e < 4; e++) acc[i][j][e] = 0.f;

    const int a_kr = (lane & 7) + ((lane & 16) ? 8 : 0);
    const int a_mc = ((lane & 8) ? 8 : 0);
    const int b_row = wn * 32 + (lane & 7) + ((lane >> 4) & 1) * 8;
    const int b_kg  = (lane >> 3) & 1;

    const int nchunks = K >> 6;

    auto prefetch = [&](int chunk, int stage) {
        const uint32_t sbuf = sbase + stage * ST_SIZE;
        const int k0 = chunk << 6;
        // A: [64 k][128 n] = 1024 16B chunks per plane (4 x 256 threads)
        #pragma unroll
        for (int r = 0; r < 4; r++) {
            const int u = tid + 256 * r;
            const int row = u >> 4, blk = u & 15;
            const uint32_t d = (uint32_t)(row * GROW + blk * 16);
            const size_t aidx = (size_t)(k0 + row) * NN + n0 + blk * 8;
            CP16(sbuf + ST_A_HI + d, Abh + aidx);
            CP16(sbuf + ST_A_LO + d, Abl + aidx);
        }
        // B: [64 o][64 k] = 512 16B chunks per plane (2 x 256 threads)
        #pragma unroll
        for (int r = 0; r < 2; r++) {
            const int u = tid + 256 * r;
            const int row = u >> 3, g = u & 7;
            const uint32_t d = (uint32_t)(row * BROW + g * 16);
            const size_t widx = (size_t)(o0 + row) * K + k0 + g * 8;
            CP16(sbuf + ST_B_HI + d, Wh + widx);
            CP16(sbuf + ST_B_LO + d, Wl + widx);
        }
    };

    prefetch(0, 0); CP_COMMIT();

    for (int chunk = 0; chunk < nchunks; chunk++) {
        const int cur = chunk & 1;
        if (chunk + 1 < nchunks) prefetch(chunk + 1, cur ^ 1);
        CP_COMMIT();
        CP_WAIT1();
        __syncthreads();

        const uint32_t sbuf = sbase + cur * ST_SIZE;
        #pragma unroll
        for (int ks = 0; ks < 4; ks++) {
            uint32_t bh[8], bl[8];
            #pragma unroll
            for (int ng = 0; ng < 2; ng++) {
                const uint32_t boff =
                    (uint32_t)((b_row + ng * 16) * BROW + (ks * 2 + b_kg) * 16);
                ldmx4(&bh[ng * 4], sbuf + ST_B_HI + boff);
                ldmx4(&bl[ng * 4], sbuf + ST_B_LO + boff);
            }
            #pragma unroll
            for (int mf = 0; mf < 2; mf++) {
                const uint32_t aoff = (uint32_t)((ks * 16 + a_kr) * GROW
                                   + (wm * 32 + mf * 16 + a_mc) * 2);
                uint32_t ah[4], al[4];
                ldmx4t(ah, sbuf + ST_A_HI + aoff);
                ldmx4t(al, sbuf + ST_A_LO + aoff);
                #pragma unroll
                for (int nf = 0; nf < 4; nf++) {
                    const int bi = (nf >> 1) * 4 + (nf & 1) * 2;
                    mma16816(acc[mf][nf], ah, bh[bi], bh[bi + 1]);
                    mma16816(acc[mf][nf], ah, bl[bi], bl[bi + 1]);
                    mma16816(acc[mf][nf], al, bh[bi], bh[bi + 1]);
                }
            }
        }
        __syncthreads();
    }

    // Epilogue: transpose via smem [64 o][132 m], coalesced writes
    float* Cs = (float*)smem;
    #pragma unroll
    for (int mf = 0; mf < 2; mf++) {
        const int m = wm * 32 + mf * 16 + (lane >> 2);
        #pragma unroll
        for (int nf = 0; nf < 4; nf++) {
            const int ol = wn * 32 + nf * 8 + (lane & 3) * 2;
            Cs[ ol      * 132 + m    ] = acc[mf][nf][0];
            Cs[(ol + 1) * 132 + m    ] = acc[mf][nf][1];
            Cs[ ol      * 132 + m + 8] = acc[mf][nf][2];
            Cs[(ol + 1) * 132 + m + 8] = acc[mf][nf][3];
        }
    }
    __syncthreads();

    #pragma unroll 4
    for (int i = 0; i < 32; i++) {
        const int idx = tid + 256 * i;
        const int ol = idx >> 7;
        const int m  = idx & 127;
        const int o  = o0 + ol;
        float v = Cs[ol * 132 + m] + bias[o];
        const size_t gidx = ((size_t)b * O + o) * NN + n0 + m;
        if (EPI == 1) {
            ((float*)out1)[gidx] = v + res[gidx];
        } else {
            if (EPI == 4) v = 0.5f * v * (1.f + erff(v * 0.7071067811865476f));
            const __nv_bfloat16 h = __float2bfloat16(v);
            ((__nv_bfloat16*)out1)[gidx] = h;
            ((__nv_bfloat16*)out2)[gidx] = __float2bfloat16(v - __bfloat162float(h));
        }
    }
}

// ---------------------------------------------------------------------------
// Pipelined MMA flash attention (round-11 measured config).
// QK: 3-product split. PV: single bf16 (P hi, V hi plane).
// ---------------------------------------------------------------------------
#define AST_KHI 0
#define AST_KLO 13056
#define AST_VHI 26112
#define AST_SIZE 39168
#define AT_BIAS_OFF 78336
#define AT_SMEM_TOTAL (78336 + 35 * 64 * 4)   // 87296
#define ATT_SCALE 0.14433756729740643f

__global__ __launch_bounds__(256, 1)
void attn_kernel(const __nv_bfloat16* __restrict__ QKVh,
                 const __nv_bfloat16* __restrict__ QKVl,
                 const float* __restrict__ rpb,
                 __nv_bfloat16* __restrict__ Oh, __nv_bfloat16* __restrict__ Ol)
{
    extern __shared__ __align__(16) char smem[];
    const uint32_t sb = smem_to_u32(smem);
    const int tid = threadIdx.x, lane = tid & 31, w = tid >> 5;
    const int qb = blockIdx.x, h = blockIdx.y, b = blockIdx.z;

    float* bias_s = (float*)(smem + AT_BIAS_OFF);
    for (int e = tid; e < 35 * 63; e += 256) {
        const int a = e / 63, dw = e % 63;
        bias_s[a * 64 + dw] = rpb[((size_t)((a + qb * 4) * 63 + dw)) * NHH + h];
    }

    const size_t qrow = (size_t)(b * QKVO + h * HDD) * NN;
    const size_t krow = (size_t)(b * QKVO + MIDD + h * HDD) * NN;
    const size_t vrow = (size_t)(b * QKVO + 2 * MIDD + h * HDD) * NN;

    auto prefetchKV = [&](int kb, int stage) {
        const uint32_t sbuf = sb + stage * AST_SIZE;
        #pragma unroll
        for (int r = 0; r < 3; r++) {
            const int u = tid + 256 * r;
            const int row = u >> 4, blk = u & 15;
            const uint32_t d = (uint32_t)(row * GROW + blk * 16);
            const size_t kidx = krow + (size_t)row * NN + kb * 128 + blk * 8;
            const size_t vidx = vrow + (size_t)row * NN + kb * 128 + blk * 8;
            CP16(sbuf + AST_KHI + d, QKVh + kidx);
            CP16(sbuf + AST_KLO + d, QKVl + kidx);
            CP16(sbuf + AST_VHI + d, QKVh + vidx);
        }
    };

    {   // stage Q into stage-1 K planes
        const uint32_t sbuf = sb + AST_SIZE;
        #pragma unroll
        for (int r = 0; r < 3; r++) {
            const int u = tid + 256 * r;
            const int row = u >> 4, blk = u & 15;
            const uint32_t d = (uint32_t)(row * GROW + blk * 16);
            const size_t qidx = qrow + (size_t)row * NN + qb * 128 + blk * 8;
            CP16(sbuf + AST_KHI + d, QKVh + qidx);
            CP16(sbuf + AST_KLO + d, QKVl + qidx);
        }
    }
    CP_COMMIT();
    prefetchKV(0, 0); CP_COMMIT();
    CP_WAIT1();
    __syncthreads();

    uint32_t qfh[3][4], qfl[3][4];
    {
        const int q_dr = (lane & 7) + ((lane & 16) ? 8 : 0);
        const int q_mc = ((lane & 8) ? 8 : 0);
        #pragma unroll
        for (int ks = 0; ks < 3; ks++) {
            const uint32_t off = (uint32_t)((ks * 16 + q_dr) * GROW
                               + (w * 16 + q_mc) * 2);
            ldmx4t(qfh[ks], sb + AST_SIZE + AST_KHI + off);
            ldmx4t(qfl[ks], sb + AST_SIZE + AST_KLO + off);
        }
    }
    __syncthreads();

    float of[6][4];
    #pragma unroll
    for (int i = 0; i < 6; i++)
        #pragma unroll
        for (int e = 0; e < 4; e++) of[i][e] = 0.f;
    float mrow0 = -1e30f, mrow1 = -1e30f, lrow0 = 0.f, lrow1 = 0.f;

    const int trow0 = w * 16 + (lane >> 2);
    const int hn0 = trow0 >> 5, wn0 = trow0 & 31;
    const int trow1 = trow0 + 8;
    const int hn1 = trow1 >> 5, wn1 = trow1 & 31;

    const int b_dr = (lane & 7) + ((lane & 8) ? 8 : 0);
    const int b_kc = ((lane & 16) ? 8 : 0);
    const int v_dr = (lane & 7) + ((lane & 16) ? 8 : 0);
    const int v_kc = ((lane & 8) ? 8 : 0);

    for (int kb = 0; kb < 8; kb++) {
        const int cur = kb & 1;
        if (kb + 1 < 8) prefetchKV(kb + 1, cur ^ 1);
        CP_COMMIT();
        CP_WAIT1();
        __syncthreads();
        const uint32_t sbuf = sb + cur * AST_SIZE;

        float s[16][4];
        #pragma unroll
        for (int i = 0; i < 16; i++)
            #pragma unroll
            for (int e = 0; e < 4; e++) s[i][e] = 0.f;

        #pragma unroll
        for (int ks = 0; ks < 3; ks++) {
            #pragma unroll
            for (int np = 0; np < 8; np++) {
                const uint32_t off = (uint32_t)((ks * 16 + b_dr) * GROW
                                   + (np * 16 + b_kc) * 2);
                uint32_t kh4[4], kl4[4];
                ldmx4t(kh4, sbuf + AST_KHI + off);
                ldmx4t(kl4, sbuf + AST_KLO + off);
                mma16816(s[2*np],   qfh[ks], kh4[0], kh4[1]);
                mma16816(s[2*np],   qfh[ks], kl4[0], kl4[1]);
                mma16816(s[2*np],   qfl[ks], kh4[0], kh4[1]);
                mma16816(s[2*np+1], qfh[ks], kh4[2], kh4[3]);
                mma16816(s[2*np+1], qfh[ks], kl4[2], kl4[3]);
                mma16816(s[2*np+1], qfl[ks], kh4[2], kh4[3]);
            }
        }

        float mx0 = -1e30f, mx1 = -1e30f;
        #pragma unroll
        for (int nf = 0; nf < 16; nf++) {
            const int j0 = nf * 8 + (lane & 3) * 2;
            const int hm = kb * 4 + (j0 >> 5);
            const int wm = j0 & 31;
            const float* br0 = bias_s + (hn0 + 31 - hm) * 64 + (wn0 - wm + 31);
            const float* br1 = bias_s + (hn1 + 31 - hm) * 64 + (wn1 - wm + 31);
            s[nf][0] = s[nf][0] * ATT_SCALE + br0[0];
            s[nf][1] = s[nf][1] * ATT_SCALE + br0[-1];
            s[nf][2] = s[nf][2] * ATT_SCALE + br1[0];
            s[nf][3] = s[nf][3] * ATT_SCALE + br1[-1];
            mx0 = fmaxf(mx0, fmaxf(s[nf][0], s[nf][1]));
            mx1 = fmaxf(mx1, fmaxf(s[nf][2], s[nf][3]));
        }
        mx0 = fmaxf(mx0, __shfl_xor_sync(0xffffffffu, mx0, 1));
        mx0 = fmaxf(mx0, __shfl_xor_sync(0xffffffffu, mx0, 2));
        mx1 = fmaxf(mx1, __shfl_xor_sync(0xffffffffu, mx1, 1));
        mx1 = fmaxf(mx1, __shfl_xor_sync(0xffffffffu, mx1, 2));
        const float mn0 = fmaxf(mrow0, mx0), mn1 = fmaxf(mrow1, mx1);
        const float c0 = __expf(mrow0 - mn0), c1 = __expf(mrow1 - mn1);
        mrow0 = mn0; mrow1 = mn1;
        #pragma unroll
        for (int nf = 0; nf < 6; nf++) {
            of[nf][0] *= c0; of[nf][1] *= c0;
            of[nf][2] *= c1; of[nf][3] *= c1;
        }
        float sum0 = 0.f, sum1 = 0.f;
        #pragma unroll
        for (int nf = 0; nf < 16; nf++) {
            s[nf][0] = __expf(s[nf][0] - mn0); sum0 += s[nf][0];
            s[nf][1] = __expf(s[nf][1] - mn0); sum0 += s[nf][1];
            s[nf][2] = __expf(s[nf][2] - mn1); sum1 += s[nf][2];
            s[nf][3] = __expf(s[nf][3] - mn1); sum1 += s[nf][3];
        }
        sum0 += __shfl_xor_sync(0xffffffffu, sum0, 1);
        sum0 += __shfl_xor_sync(0xffffffffu, sum0, 2);
        sum1 += __shfl_xor_sync(0xffffffffu, sum1, 1);
        sum1 += __shfl_xor_sync(0xffffffffu, sum1, 2);
        lrow0 = lrow0 * c0 + sum0;
        lrow1 = lrow1 * c1 + sum1;

        // O += P V : P single bf16 (hi only), V hi plane only
        #pragma unroll
        for (int ks = 0; ks < 8; ks++) {
            uint32_t ah[4];
            {
                const float f[8] = {s[2*ks][0],   s[2*ks][1],   s[2*ks][2],   s[2*ks][3],
                                    s[2*ks+1][0], s[2*ks+1][1], s[2*ks+1][2], s[2*ks+1][3]};
                #pragma unroll
                for (int i = 0; i < 4; i++) {
                    __nv_bfloat162 hh(__float2bfloat16(f[2*i]), __float2bfloat16(f[2*i+1]));
                    ah[i] = *(uint32_t*)&hh;
                }
            }
            #pragma unroll
            for (int np = 0; np < 3; np++) {
                const uint32_t off = (uint32_t)((np * 16 + v_dr) * GROW
                                   + (ks * 16 + v_kc) * 2);
                uint32_t vh4[4];
                ldmx4(vh4, sbuf + AST_VHI + off);
                mma16816(of[2*np],   ah, vh4[0], vh4[1]);
                mma16816(of[2*np+1], ah, vh4[2], vh4[3]);
            }
        }
        __syncthreads();
    }

    const float inv0 = 1.f / lrow0, inv1 = 1.f / lrow1;
    float* Os = (float*)smem;   // [48 d][132]
    #pragma unroll
    for (int nf = 0; nf < 6; nf++) {
        const int d0 = nf * 8 + (lane & 3) * 2;
        const int t0 = w * 16 + (lane >> 2);
        Os[ d0      * 132 + t0    ] = of[nf][0] * inv0;
        Os[(d0 + 1) * 132 + t0    ] = of[nf][1] * inv0;
        Os[ d0      * 132 + t0 + 8] = of[nf][2] * inv1;
        Os[(d0 + 1) * 132 + t0 + 8] = of[nf][3] * inv1;
    }
    __syncthreads();
    const size_t orow = (size_t)(b * MIDD + h * HDD) * NN;
    #pragma unroll
    for (int i = 0; i < 24; i++) {
        const int u = tid + 256 * i;
        const int d = u >> 7, t = u & 127;
        const float v = Os[d * 132 + t];
        const size_t gidx = orow + (size_t)d * NN + qb * 128 + t;
        const __nv_bfloat16 hh = __float2bfloat16(v);
        Oh[gidx] = hh;
        Ol[gidx] = __float2bfloat16(v - __bfloat162float(hh));
    }
}

// ---------------------------------------------------------------------------
extern "C" void kernel_launch(void* const* d_in, const int* in_sizes, int n_in,
                              void* d_out, int out_size)
{
    const float* x     = (const float*)d_in[0];
    const float* rpb   = (const float*)d_in[1];
    const float* ln1_g = (const float*)d_in[3];
    const float* ln1_b = (const float*)d_in[4];
    const float* ln2_g = (const float*)d_in[5];
    const float* ln2_b = (const float*)d_in[6];
    const float* wq    = (const float*)d_in[7];
    const float* bq    = (const float*)d_in[8];
    const float* wkv   = (const float*)d_in[9];
    const float* bkv   = (const float*)d_in[10];
    const float* wproj = (const float*)d_in[11];
    const float* bproj = (const float*)d_in[12];
    const float* w1    = (const float*)d_in[13];
    const float* b1    = (const float*)d_in[14];
    const float* w2    = (const float*)d_in[15];
    const float* b2    = (const float*)d_in[16];
    float* out = (float*)d_out;

    __nv_bfloat16 *p_lnh, *p_lnl, *p_qkvh, *p_qkvl,
                  *p_aoh, *p_aol, *p_mh, *p_ml, *p_wh, *p_wl;
    float *p_y1, *p_bqkv;
    cudaGetSymbolAddress((void**)&p_lnh,  g_lnh);
    cudaGetSymbolAddress((void**)&p_lnl,  g_lnl);
    cudaGetSymbolAddress((void**)&p_qkvh, g_qkvh);
    cudaGetSymbolAddress((void**)&p_qkvl, g_qkvl);
    cudaGetSymbolAddress((void**)&p_aoh,  g_aoh);
    cudaGetSymbolAddress((void**)&p_aol,  g_aol);
    cudaGetSymbolAddress((void**)&p_mh,   g_mh);
    cudaGetSymbolAddress((void**)&p_ml,   g_ml);
    cudaGetSymbolAddress((void**)&p_y1,   g_y1);
    cudaGetSymbolAddress((void**)&p_wh,   g_wh);
    cudaGetSymbolAddress((void**)&p_wl,   g_wl);
    cudaGetSymbolAddress((void**)&p_bqkv, g_bqkv);

    cudaFuncSetAttribute(mma_gemm<1>, cudaFuncAttributeMaxDynamicSharedMemorySize, SM_GEMM_TOTAL);
    cudaFuncSetAttribute(mma_gemm<3>, cudaFuncAttributeMaxDynamicSharedMemorySize, SM_GEMM_TOTAL);
    cudaFuncSetAttribute(mma_gemm<4>, cudaFuncAttributeMaxDynamicSharedMemorySize, SM_GEMM_TOTAL);
    cudaFuncSetAttribute(attn_kernel, cudaFuncAttributeMaxDynamicSharedMemorySize, AT_SMEM_TOTAL);

    prep_kernel<<<(WTOTAL + 255) / 256, 256>>>(wq, wkv, wproj, w1, w2, bq, bkv,
                                               p_wh, p_wl, p_bqkv);

    const dim3 lnGrid(NN / 256, BB);

    ln_kernel<<<lnGrid, 256>>>(x, ln1_g, ln1_b, p_lnh, p_lnl);
    mma_gemm<3><<<dim3(NN/128, QKVO/64, BB), 256, SM_GEMM_TOTAL>>>(
        p_wh + WOFF_Q, p_wl + WOFF_Q, p_lnh, p_lnl, p_bqkv, nullptr,
        p_qkvh, p_qkvl, QKVO, CC);
    attn_kernel<<<dim3(NN/128, NHH, BB), 256, AT_SMEM_TOTAL>>>(
        p_qkvh, p_qkvl, rpb, p_aoh, p_aol);
    mma_gemm<1><<<dim3(NN/128, CC/64, BB), 256, SM_GEMM_TOTAL>>>(
        p_wh + WOFF_PROJ, p_wl + WOFF_PROJ, p_aoh, p_aol, bproj, x, p_y1, nullptr, CC, MIDD);
    ln_kernel<<<lnGrid, 256>>>(p_y1, ln2_g, ln2_b, p_lnh, p_lnl);
    mma_gemm<4><<<dim3(NN/128, HIDD/64, BB), 256, SM_GEMM_TOTAL>>>(
        p_wh + WOFF_W1, p_wl + WOFF_W1, p_lnh, p_lnl, b1, nullptr, p_mh, p_ml, HIDD, CC);
    mma_gemm<1><<<dim3(NN/128, CC/64, BB), 256, SM_GEMM_TOTAL>>>(
        p_wh + WOFF_W2, p_wl + WOFF_W2, p_mh, p_ml, b2, p_y1, out, nullptr, CC, HIDD);
}

// round 14
// speedup vs baseline: 1.3252x; 1.2271x over previous
#include <cuda_runtime.h>
#include <cuda_bf16.h>
#include <cstdint>

// ---------------------------------------------------------------------------
// ViT block. B=16, C=384, N=1024 (32x32), NH=8, HD=48, MID=384, HID=1536.
// fp32 I/O; activations as TWO bf16 planes (hi, lo), [c][n] layout.
// mma.sync m16n8k16 bf16. Precision scheme (calibrated via round-11 data):
//   GEMMs:      act(hi+lo) x W(hi)  -> 2 products   (W single bf16)
//   attn QK:    q(hi+lo)  x K(hi)   -> 2 products
//   attn PV:    P(hi)     x V(hi)   -> 1 product
// cp.async 2-stage pipelines. GEMM: 128x64 tile, 256 thr, 2 CTAs/SM.
// ---------------------------------------------------------------------------

#define BB   16
#define CC   384
#define NN   1024
#define NHH  8
#define HDD  48
#define MIDD 384
#define HIDD 1536
#define QKVO (3 * MIDD)   // 1152

__device__ __nv_bfloat16 g_lnh [BB * CC   * NN], g_lnl [BB * CC   * NN];
__device__ __nv_bfloat16 g_qkvh[BB * QKVO * NN], g_qkvl[BB * QKVO * NN];
__device__ __nv_bfloat16 g_aoh [BB * MIDD * NN], g_aol [BB * MIDD * NN];
__device__ __nv_bfloat16 g_mh  [BB * HIDD * NN], g_ml  [BB * HIDD * NN];
__device__ float         g_y1  [BB * CC   * NN];
__device__ float         g_bqkv[QKVO];
#define WOFF_Q    0
#define WOFF_KV   147456
#define WOFF_PROJ 442368
#define WOFF_W1   589824
#define WOFF_W2   1179648
#define WTOTAL    1769472
__device__ __nv_bfloat16 g_wh[WTOTAL];   // weights: single bf16 plane

__device__ __forceinline__ uint32_t smem_to_u32(const void* p) {
    uint32_t a;
    asm("{ .reg .u64 t; cvta.to.shared.u64 t, %1; cvt.u32.u64 %0, t; }" : "=r"(a) : "l"(p));
    return a;
}
__device__ __forceinline__ void ldmx4(uint32_t* r, uint32_t addr) {
    asm volatile("ldmatrix.sync.aligned.m8n8.x4.shared.b16 {%0,%1,%2,%3}, [%4];"
                 : "=r"(r[0]), "=r"(r[1]), "=r"(r[2]), "=r"(r[3]) : "r"(addr));
}
__device__ __forceinline__ void ldmx4t(uint32_t* r, uint32_t addr) {
    asm volatile("ldmatrix.sync.aligned.m8n8.x4.trans.shared.b16 {%0,%1,%2,%3}, [%4];"
                 : "=r"(r[0]), "=r"(r[1]), "=r"(r[2]), "=r"(r[3]) : "r"(addr));
}
__device__ __forceinline__ void mma16816(float* c, const uint32_t* a,
                                         uint32_t b0, uint32_t b1) {
    asm volatile("mma.sync.aligned.m16n8k16.row.col.f32.bf16.bf16.f32 "
                 "{%0,%1,%2,%3}, {%4,%5,%6,%7}, {%8,%9}, {%0,%1,%2,%3};"
                 : "+f"(c[0]), "+f"(c[1]), "+f"(c[2]), "+f"(c[3])
                 : "r"(a[0]), "r"(a[1]), "r"(a[2]), "r"(a[3]), "r"(b0), "r"(b1));
}
#define CP16(dst, src) \
    asm volatile("cp.async.cg.shared.global [%0], [%1], 16;" :: "r"(dst), "l"(src))
#define CP_COMMIT() asm volatile("cp.async.commit_group;" ::: "memory")
#define CP_WAIT1()  asm volatile("cp.async.wait_group 1;" ::: "memory")

// ---------------------------------------------------------------------------
__global__ __launch_bounds__(256)
void prep_kernel(const float* __restrict__ wq, const float* __restrict__ wkv,
                 const float* __restrict__ wproj, const float* __restrict__ w1,
                 const float* __restrict__ w2,
                 const float* __restrict__ bq, const float* __restrict__ bkv,
                 __nv_bfloat16* __restrict__ wh, float* __restrict__ bqkv)
{
    const int i = blockIdx.x * 256 + threadIdx.x;
    if (i < WTOTAL) {
        const float* src; int off;
        if      (i < WOFF_KV)   { src = wq;    off = i; }
        else if (i < WOFF_PROJ) { src = wkv;   off = i - WOFF_KV; }
        else if (i < WOFF_W1)   { src = wproj; off = i - WOFF_PROJ; }
        else if (i < WOFF_W2)   { src = w1;    off = i - WOFF_W1; }
        else                    { src = w2;    off = i - WOFF_W2; }
        wh[i] = __float2bfloat16(src[off]);
    }
    if (i < QKVO) bqkv[i] = (i < MIDD) ? bq[i] : bkv[i - MIDD];
}

__global__ __launch_bounds__(256)
void ln_kernel(const float* __restrict__ x, const float* __restrict__ g,
               const float* __restrict__ beta,
               __nv_bfloat16* __restrict__ oh, __nv_bfloat16* __restrict__ ol)
{
    const int b = blockIdx.y;
    const int n = blockIdx.x * 256 + threadIdx.x;
    const float* xp = x + (size_t)b * CC * NN + n;

    float sum = 0.f, sq = 0.f;
    #pragma unroll 4
    for (int c = 0; c < CC; c++) {
        float v = xp[(size_t)c * NN];
        sum += v; sq += v * v;
    }
    const float mean = sum * (1.f / CC);
    float var = sq * (1.f / CC) - mean * mean;
    var = var < 0.f ? 0.f : var;
    const float rstd = rsqrtf(var + 1e-5f);

    __nv_bfloat16* ph = oh + (size_t)b * CC * NN + n;
    __nv_bfloat16* pl = ol + (size_t)b * CC * NN + n;
    #pragma unroll 4
    for (int c = 0; c < CC; c++) {
        float v = (xp[(size_t)c * NN] - mean) * rstd * g[c] + beta[c];
        const __nv_bfloat16 h = __float2bfloat16(v);
        ph[(size_t)c * NN] = h;
        pl[(size_t)c * NN] = __float2bfloat16(v - __bfloat162float(h));
    }
}

// ---------------------------------------------------------------------------
// Pipelined HMMA GEMM, CTA 128(m) x 64(o), 256 threads, 2 CTAs/SM.
// A: K-major smem [64 k][136h] (272B rows, trans frags), hi+lo planes.
// B: o-major smem [64 o][72h] (144B rows, non-trans frags), single plane.
// Per fragment: acc += ah*W; acc += al*W  (2 MMAs).
// EPI: 1 = fp32 + residual; 3 = hi/lo planes; 4 = GELU + planes.
// ---------------------------------------------------------------------------
#define GROW 272
#define BROW 144
#define ST_A_HI 0
#define ST_A_LO 17408
#define ST_B_HI 34816
#define ST_SIZE 44032
#define SM_GEMM_TOTAL (2 * ST_SIZE)   // 88064 (2 CTAs -> 176128 smem/SM)

template<int EPI>
__global__ __launch_bounds__(256, 2)
void mma_gemm(const __nv_bfloat16* __restrict__ Wh,
              const __nv_bfloat16* __restrict__ Ah, const __nv_bfloat16* __restrict__ Al,
              const float* __restrict__ bias, const float* __restrict__ res,
              void* __restrict__ out1, void* __restrict__ out2, int O, int K)
{
    extern __shared__ __align__(16) char smem[];
    const uint32_t sbase = smem_to_u32(smem);

    const int b   = blockIdx.z;
    const int n0  = blockIdx.x * 128;
    const int o0  = blockIdx.y * 64;
    const int tid = threadIdx.x;
    const int wid = tid >> 5;
    const int lane = tid & 31;
    const int wm = wid & 3;
    const int wn = wid >> 2;

    const __nv_bfloat16* Abh = Ah + (size_t)b * K * NN;
    const __nv_bfloat16* Abl = Al + (size_t)b * K * NN;

    float acc[2][4][4];
    #pragma unroll
    for (int i = 0; i < 2; i++)
        #pragma unroll
        for (int j = 0; j < 4; j++)
            #pragma unroll
            for (int e = 0; e < 4; e++) acc[i][j][e] = 0.f;

    const int a_kr = (lane & 7) + ((lane & 16) ? 8 : 0);
    const int a_mc = ((lane & 8) ? 8 : 0);
    const int b_row = wn * 32 + (lane & 7) + ((lane >> 4) & 1) * 8;
    const int b_kg  = (lane >> 3) & 1;

    const int nchunks = K >> 6;

    auto prefetch = [&](int chunk, int stage) {
        const uint32_t sbuf = sbase + stage * ST_SIZE;
        const int k0 = chunk << 6;
        #pragma unroll
        for (int r = 0; r < 4; r++) {
            const int u = tid + 256 * r;
            const int row = u >> 4, blk = u & 15;
            const uint32_t d = (uint32_t)(row * GROW + blk * 16);
            const size_t aidx = (size_t)(k0 + row) * NN + n0 + blk * 8;
            CP16(sbuf + ST_A_HI + d, Abh + aidx);
            CP16(sbuf + ST_A_LO + d, Abl + aidx);
        }
        #pragma unroll
        for (int r = 0; r < 2; r++) {
            const int u = tid + 256 * r;
            const int row = u >> 3, g = u & 7;
            const uint32_t d = (uint32_t)(row * BROW + g * 16);
            const size_t widx = (size_t)(o0 + row) * K + k0 + g * 8;
            CP16(sbuf + ST_B_HI + d, Wh + widx);
        }
    };

    prefetch(0, 0); CP_COMMIT();

    for (int chunk = 0; chunk < nchunks; chunk++) {
        const int cur = chunk & 1;
        if (chunk + 1 < nchunks) prefetch(chunk + 1, cur ^ 1);
        CP_COMMIT();
        CP_WAIT1();
        __syncthreads();

        const uint32_t sbuf = sbase + cur * ST_SIZE;
        #pragma unroll
        for (int ks = 0; ks < 4; ks++) {
            uint32_t bh[8];
            #pragma unroll
            for (int ng = 0; ng < 2; ng++) {
                const uint32_t boff =
                    (uint32_t)((b_row + ng * 16) * BROW + (ks * 2 + b_kg) * 16);
                ldmx4(&bh[ng * 4], sbuf + ST_B_HI + boff);
            }
            #pragma unroll
            for (int mf = 0; mf < 2; mf++) {
                const uint32_t aoff = (uint32_t)((ks * 16 + a_kr) * GROW
                                   + (wm * 32 + mf * 16 + a_mc) * 2);
                uint32_t ah[4], al[4];
                ldmx4t(ah, sbuf + ST_A_HI + aoff);
                ldmx4t(al, sbuf + ST_A_LO + aoff);
                #pragma unroll
                for (int nf = 0; nf < 4; nf++) {
                    const int bi = (nf >> 1) * 4 + (nf & 1) * 2;
                    mma16816(acc[mf][nf], ah, bh[bi], bh[bi + 1]);
                    mma16816(acc[mf][nf], al, bh[bi], bh[bi + 1]);
                }
            }
        }
        __syncthreads();
    }

    float* Cs = (float*)smem;  // [64 o][132 m]
    #pragma unroll
    for (int mf = 0; mf < 2; mf++) {
        const int m = wm * 32 + mf * 16 + (lane >> 2);
        #pragma unroll
        for (int nf = 0; nf < 4; nf++) {
            const int ol = wn * 32 + nf * 8 + (lane & 3) * 2;
            Cs[ ol      * 132 + m    ] = acc[mf][nf][0];
            Cs[(ol + 1) * 132 + m    ] = acc[mf][nf][1];
            Cs[ ol      * 132 + m + 8] = acc[mf][nf][2];
            Cs[(ol + 1) * 132 + m + 8] = acc[mf][nf][3];
        }
    }
    __syncthreads();

    #pragma unroll 4
    for (int i = 0; i < 32; i++) {
        const int idx = tid + 256 * i;
        const int ol = idx >> 7;
        const int m  = idx & 127;
        const int o  = o0 + ol;
        float v = Cs[ol * 132 + m] + bias[o];
        const size_t gidx = ((size_t)b * O + o) * NN + n0 + m;
        if (EPI == 1) {
            ((float*)out1)[gidx] = v + res[gidx];
        } else {
            if (EPI == 4) v = 0.5f * v * (1.f + erff(v * 0.7071067811865476f));
            const __nv_bfloat16 h = __float2bfloat16(v);
            ((__nv_bfloat16*)out1)[gidx] = h;
            ((__nv_bfloat16*)out2)[gidx] = __float2bfloat16(v - __bfloat162float(h));
        }
    }
}

// ---------------------------------------------------------------------------
// Pipelined MMA flash attention.
// QK: q(hi+lo) x K(hi) = 2 products. PV: P(hi) x V(hi) = 1 product.
// Stages hold K hi + V hi only; Q lo staged through stage-1 V slot.
// ---------------------------------------------------------------------------
#define AST_KHI 0
#define AST_VHI 13056
#define AST_SIZE 26112
#define AT_BIAS_OFF 52224
#define AT_SMEM_TOTAL (52224 + 35 * 64 * 4)   // 61184
#define ATT_SCALE 0.14433756729740643f

__global__ __launch_bounds__(256, 1)
void attn_kernel(const __nv_bfloat16* __restrict__ QKVh,
                 const __nv_bfloat16* __restrict__ QKVl,
                 const float* __restrict__ rpb,
                 __nv_bfloat16* __restrict__ Oh, __nv_bfloat16* __restrict__ Ol)
{
    extern __shared__ __align__(16) char smem[];
    const uint32_t sb = smem_to_u32(smem);
    const int tid = threadIdx.x, lane = tid & 31, w = tid >> 5;
    const int qb = blockIdx.x, h = blockIdx.y, b = blockIdx.z;

    float* bias_s = (float*)(smem + AT_BIAS_OFF);
    for (int e = tid; e < 35 * 63; e += 256) {
        const int a = e / 63, dw = e % 63;
        bias_s[a * 64 + dw] = rpb[((size_t)((a + qb * 4) * 63 + dw)) * NHH + h];
    }

    const size_t qrow = (size_t)(b * QKVO + h * HDD) * NN;
    const size_t krow = (size_t)(b * QKVO + MIDD + h * HDD) * NN;
    const size_t vrow = (size_t)(b * QKVO + 2 * MIDD + h * HDD) * NN;

    auto prefetchKV = [&](int kb, int stage) {
        const uint32_t sbuf = sb + stage * AST_SIZE;
        #pragma unroll
        for (int r = 0; r < 3; r++) {
            const int u = tid + 256 * r;
            const int row = u >> 4, blk = u & 15;
            const uint32_t d = (uint32_t)(row * GROW + blk * 16);
            const size_t kidx = krow + (size_t)row * NN + kb * 128 + blk * 8;
            const size_t vidx = vrow + (size_t)row * NN + kb * 128 + blk * 8;
            CP16(sbuf + AST_KHI + d, QKVh + kidx);
            CP16(sbuf + AST_VHI + d, QKVh + vidx);
        }
    };

    {   // stage Q: hi -> stage-1 K slot, lo -> stage-1 V slot
        const uint32_t sbuf = sb + AST_SIZE;
        #pragma unroll
        for (int r = 0; r < 3; r++) {
            const int u = tid + 256 * r;
            const int row = u >> 4, blk = u & 15;
            const uint32_t d = (uint32_t)(row * GROW + blk * 16);
            const size_t qidx = qrow + (size_t)row * NN + qb * 128 + blk * 8;
            CP16(sbuf + AST_KHI + d, QKVh + qidx);
            CP16(sbuf + AST_VHI + d, QKVl + qidx);
        }
    }
    CP_COMMIT();
    prefetchKV(0, 0); CP_COMMIT();
    CP_WAIT1();
    __syncthreads();

    uint32_t qfh[3][4], qfl[3][4];
    {
        const int q_dr = (lane & 7) + ((lane & 16) ? 8 : 0);
        const int q_mc = ((lane & 8) ? 8 : 0);
        #pragma unroll
        for (int ks = 0; ks < 3; ks++) {
            const uint32_t off = (uint32_t)((ks * 16 + q_dr) * GROW
                               + (w * 16 + q_mc) * 2);
            ldmx4t(qfh[ks], sb + AST_SIZE + AST_KHI + off);
            ldmx4t(qfl[ks], sb + AST_SIZE + AST_VHI + off);
        }
    }
    __syncthreads();

    float of[6][4];
    #pragma unroll
    for (int i = 0; i < 6; i++)
        #pragma unroll
        for (int e = 0; e < 4; e++) of[i][e] = 0.f;
    float mrow0 = -1e30f, mrow1 = -1e30f, lrow0 = 0.f, lrow1 = 0.f;

    const int trow0 = w * 16 + (lane >> 2);
    const int hn0 = trow0 >> 5, wn0 = trow0 & 31;
    const int trow1 = trow0 + 8;
    const int hn1 = trow1 >> 5, wn1 = trow1 & 31;

    const int b_dr = (lane & 7) + ((lane & 8) ? 8 : 0);
    const int b_kc = ((lane & 16) ? 8 : 0);
    const int v_dr = (lane & 7) + ((lane & 16) ? 8 : 0);
    const int v_kc = ((lane & 8) ? 8 : 0);

    for (int kb = 0; kb < 8; kb++) {
        const int cur = kb & 1;
        if (kb + 1 < 8) prefetchKV(kb + 1, cur ^ 1);
        CP_COMMIT();
        CP_WAIT1();
        __syncthreads();
        const uint32_t sbuf = sb + cur * AST_SIZE;

        float s[16][4];
        #pragma unroll
        for (int i = 0; i < 16; i++)
            #pragma unroll
            for (int e = 0; e < 4; e++) s[i][e] = 0.f;

        #pragma unroll
        for (int ks = 0; ks < 3; ks++) {
            #pragma unroll
            for (int np = 0; np < 8; np++) {
                const uint32_t off = (uint32_t)((ks * 16 + b_dr) * GROW
                                   + (np * 16 + b_kc) * 2);
                uint32_t kh4[4];
                ldmx4t(kh4, sbuf + AST_KHI + off);
                mma16816(s[2*np],   qfh[ks], kh4[0], kh4[1]);
                mma16816(s[2*np],   qfl[ks], kh4[0], kh4[1]);
                mma16816(s[2*np+1], qfh[ks], kh4[2], kh4[3]);
                mma16816(s[2*np+1], qfl[ks], kh4[2], kh4[3]);
            }
        }

        float mx0 = -1e30f, mx1 = -1e30f;
        #pragma unroll
        for (int nf = 0; nf < 16; nf++) {
            const int j0 = nf * 8 + (lane & 3) * 2;
            const int hm = kb * 4 + (j0 >> 5);
            const int wm = j0 & 31;
            const float* br0 = bias_s + (hn0 + 31 - hm) * 64 + (wn0 - wm + 31);
            const float* br1 = bias_s + (hn1 + 31 - hm) * 64 + (wn1 - wm + 31);
            s[nf][0] = s[nf][0] * ATT_SCALE + br0[0];
            s[nf][1] = s[nf][1] * ATT_SCALE + br0[-1];
            s[nf][2] = s[nf][2] * ATT_SCALE + br1[0];
            s[nf][3] = s[nf][3] * ATT_SCALE + br1[-1];
            mx0 = fmaxf(mx0, fmaxf(s[nf][0], s[nf][1]));
            mx1 = fmaxf(mx1, fmaxf(s[nf][2], s[nf][3]));
        }
        mx0 = fmaxf(mx0, __shfl_xor_sync(0xffffffffu, mx0, 1));
        mx0 = fmaxf(mx0, __shfl_xor_sync(0xffffffffu, mx0, 2));
        mx1 = fmaxf(mx1, __shfl_xor_sync(0xffffffffu, mx1, 1));
        mx1 = fmaxf(mx1, __shfl_xor_sync(0xffffffffu, mx1, 2));
        const float mn0 = fmaxf(mrow0, mx0), mn1 = fmaxf(mrow1, mx1);
        const float c0 = __expf(mrow0 - mn0), c1 = __expf(mrow1 - mn1);
        mrow0 = mn0; mrow1 = mn1;
        #pragma unroll
        for (int nf = 0; nf < 6; nf++) {
            of[nf][0] *= c0; of[nf][1] *= c0;
            of[nf][2] *= c1; of[nf][3] *= c1;
        }
        float sum0 = 0.f, sum1 = 0.f;
        #pragma unroll
        for (int nf = 0; nf < 16; nf++) {
            s[nf][0] = __expf(s[nf][0] - mn0); sum0 += s[nf][0];
            s[nf][1] = __expf(s[nf][1] - mn0); sum0 += s[nf][1];
            s[nf][2] = __expf(s[nf][2] - mn1); sum1 += s[nf][2];
            s[nf][3] = __expf(s[nf][3] - mn1); sum1 += s[nf][3];
        }
        sum0 += __shfl_xor_sync(0xffffffffu, sum0, 1);
        sum0 += __shfl_xor_sync(0xffffffffu, sum0, 2);
        sum1 += __shfl_xor_sync(0xffffffffu, sum1, 1);
        sum1 += __shfl_xor_sync(0xffffffffu, sum1, 2);
        lrow0 = lrow0 * c0 + sum0;
        lrow1 = lrow1 * c1 + sum1;

        #pragma unroll
        for (int ks = 0; ks < 8; ks++) {
            uint32_t ah[4];
            {
                const float f[8] = {s[2*ks][0],   s[2*ks][1],   s[2*ks][2],   s[2*ks][3],
                                    s[2*ks+1][0], s[2*ks+1][1], s[2*ks+1][2], s[2*ks+1][3]};
                #pragma unroll
                for (int i = 0; i < 4; i++) {
                    __nv_bfloat162 hh(__float2bfloat16(f[2*i]), __float2bfloat16(f[2*i+1]));
                    ah[i] = *(uint32_t*)&hh;
                }
            }
            #pragma unroll
            for (int np = 0; np < 3; np++) {
                const uint32_t off = (uint32_t)((np * 16 + v_dr) * GROW
                                   + (ks * 16 + v_kc) * 2);
                uint32_t vh4[4];
                ldmx4(vh4, sbuf + AST_VHI + off);
                mma16816(of[2*np],   ah, vh4[0], vh4[1]);
                mma16816(of[2*np+1], ah, vh4[2], vh4[3]);
            }
        }
        __syncthreads();
    }

    const float inv0 = 1.f / lrow0, inv1 = 1.f / lrow1;
    float* Os = (float*)smem;   // [48 d][132]
    #pragma unroll
    for (int nf = 0; nf < 6; nf++) {
        const int d0 = nf * 8 + (lane & 3) * 2;
        const int t0 = w * 16 + (lane >> 2);
        Os[ d0      * 132 + t0    ] = of[nf][0] * inv0;
        Os[(d0 + 1) * 132 + t0    ] = of[nf][1] * inv0;
        Os[ d0      * 132 + t0 + 8] = of[nf][2] * inv1;
        Os[(d0 + 1) * 132 + t0 + 8] = of[nf][3] * inv1;
    }
    __syncthreads();
    const size_t orow = (size_t)(b * MIDD + h * HDD) * NN;
    #pragma unroll
    for (int i = 0; i < 24; i++) {
        const int u = tid + 256 * i;
        const int d = u >> 7, t = u & 127;
        const float v = Os[d * 132 + t];
        const size_t gidx = orow + (size_t)d * NN + qb * 128 + t;
        const __nv_bfloat16 hh = __float2bfloat16(v);
        Oh[gidx] = hh;
        Ol[gidx] = __float2bfloat16(v - __bfloat162float(hh));
    }
}

// ---------------------------------------------------------------------------
extern "C" void kernel_launch(void* const* d_in, const int* in_sizes, int n_in,
                              void* d_out, int out_size)
{
    const float* x     = (const float*)d_in[0];
    const float* rpb   = (const float*)d_in[1];
    const float* ln1_g = (const float*)d_in[3];
    const float* ln1_b = (const float*)d_in[4];
    const float* ln2_g = (const float*)d_in[5];
    const float* ln2_b = (const float*)d_in[6];
    const float* wq    = (const float*)d_in[7];
    const float* bq    = (const float*)d_in[8];
    const float* wkv   = (const float*)d_in[9];
    const float* bkv   = (const float*)d_in[10];
    const float* wproj = (const float*)d_in[11];
    const float* bproj = (const float*)d_in[12];
    const float* w1    = (const float*)d_in[13];
    const float* b1    = (const float*)d_in[14];
    const float* w2    = (const float*)d_in[15];
    const float* b2    = (const float*)d_in[16];
    float* out = (float*)d_out;

    __nv_bfloat16 *p_lnh, *p_lnl, *p_qkvh, *p_qkvl,
                  *p_aoh, *p_aol, *p_mh, *p_ml, *p_wh;
    float *p_y1, *p_bqkv;
    cudaGetSymbolAddress((void**)&p_lnh,  g_lnh);
    cudaGetSymbolAddress((void**)&p_lnl,  g_lnl);
    cudaGetSymbolAddress((void**)&p_qkvh, g_qkvh);
    cudaGetSymbolAddress((void**)&p_qkvl, g_qkvl);
    cudaGetSymbolAddress((void**)&p_aoh,  g_aoh);
    cudaGetSymbolAddress((void**)&p_aol,  g_aol);
    cudaGetSymbolAddress((void**)&p_mh,   g_mh);
    cudaGetSymbolAddress((void**)&p_ml,   g_ml);
    cudaGetSymbolAddress((void**)&p_y1,   g_y1);
    cudaGetSymbolAddress((void**)&p_wh,   g_wh);
    cudaGetSymbolAddress((void**)&p_bqkv, g_bqkv);

    cudaFuncSetAttribute(mma_gemm<1>, cudaFuncAttributeMaxDynamicSharedMemorySize, SM_GEMM_TOTAL);
    cudaFuncSetAttribute(mma_gemm<3>, cudaFuncAttributeMaxDynamicSharedMemorySize, SM_GEMM_TOTAL);
    cudaFuncSetAttribute(mma_gemm<4>, cudaFuncAttributeMaxDynamicSharedMemorySize, SM_GEMM_TOTAL);
    cudaFuncSetAttribute(attn_kernel, cudaFuncAttributeMaxDynamicSharedMemorySize, AT_SMEM_TOTAL);

    prep_kernel<<<(WTOTAL + 255) / 256, 256>>>(wq, wkv, wproj, w1, w2, bq, bkv,
                                               p_wh, p_bqkv);

    const dim3 lnGrid(NN / 256, BB);

    ln_kernel<<<lnGrid, 256>>>(x, ln1_g, ln1_b, p_lnh, p_lnl);
    mma_gemm<3><<<dim3(NN/128, QKVO/64, BB), 256, SM_GEMM_TOTAL>>>(
        p_wh + WOFF_Q, p_lnh, p_lnl, p_bqkv, nullptr, p_qkvh, p_qkvl, QKVO, CC);
    attn_kernel<<<dim3(NN/128, NHH, BB), 256, AT_SMEM_TOTAL>>>(
        p_qkvh, p_qkvl, rpb, p_aoh, p_aol);
    mma_gemm<1><<<dim3(NN/128, CC/64, BB), 256, SM_GEMM_TOTAL>>>(
        p_wh + WOFF_PROJ, p_aoh, p_aol, bproj, x, p_y1, nullptr, CC, MIDD);
    ln_kernel<<<lnGrid, 256>>>(p_y1, ln2_g, ln2_b, p_lnh, p_lnl);
    mma_gemm<4><<<dim3(NN/128, HIDD/64, BB), 256, SM_GEMM_TOTAL>>>(
        p_wh + WOFF_W1, p_lnh, p_lnl, b1, nullptr, p_mh, p_ml, HIDD, CC);
    mma_gemm<1><<<dim3(NN/128, CC/64, BB), 256, SM_GEMM_TOTAL>>>(
        p_wh + WOFF_W2, p_mh, p_ml, b2, p_y1, out, nullptr, CC, HIDD);
}

// round 17
// speedup vs baseline: 1.3534x; 1.0213x over previous
#include <cuda_runtime.h>
#include <cuda_bf16.h>
#include <cstdint>

// ---------------------------------------------------------------------------
// ViT block. B=16, C=384, N=1024 (32x32), NH=8, HD=48, MID=384, HID=1536.
// fp32 I/O; activations as TWO bf16 planes (hi, lo), [c][n] layout.
// mma.sync m16n8k16 bf16. Precision (budget spent, rel_err ~4e-4 stable):
//   GEMMs: act(hi+lo) x W(hi); attn QK: q(hi+lo) x K(hi); PV: P(hi) x V(hi).
// cp.async 2-stage pipelines (UNCONDITIONAL commit per iter: keeps WAIT1
// group-count exact on the tail iteration). GEMM: 128x64 tile, 2 CTAs/SM.
// Attention: 64-key blocks, 2 CTAs/SM.
// ---------------------------------------------------------------------------

#define BB   16
#define CC   384
#define NN   1024
#define NHH  8
#define HDD  48
#define MIDD 384
#define HIDD 1536
#define QKVO (3 * MIDD)   // 1152

__device__ __nv_bfloat16 g_lnh [BB * CC   * NN], g_lnl [BB * CC   * NN];
__device__ __nv_bfloat16 g_qkvh[BB * QKVO * NN], g_qkvl[BB * QKVO * NN];
__device__ __nv_bfloat16 g_aoh [BB * MIDD * NN], g_aol [BB * MIDD * NN];
__device__ __nv_bfloat16 g_mh  [BB * HIDD * NN], g_ml  [BB * HIDD * NN];
__device__ float         g_y1  [BB * CC   * NN];
__device__ float         g_bqkv[QKVO];
#define WOFF_Q    0
#define WOFF_KV   147456
#define WOFF_PROJ 442368
#define WOFF_W1   589824
#define WOFF_W2   1179648
#define WTOTAL    1769472
__device__ __nv_bfloat16 g_wh[WTOTAL];   // weights: single bf16 plane

__device__ __forceinline__ uint32_t smem_to_u32(const void* p) {
    uint32_t a;
    asm("{ .reg .u64 t; cvta.to.shared.u64 t, %1; cvt.u32.u64 %0, t; }" : "=r"(a) : "l"(p));
    return a;
}
__device__ __forceinline__ void ldmx4(uint32_t* r, uint32_t addr) {
    asm volatile("ldmatrix.sync.aligned.m8n8.x4.shared.b16 {%0,%1,%2,%3}, [%4];"
                 : "=r"(r[0]), "=r"(r[1]), "=r"(r[2]), "=r"(r[3]) : "r"(addr));
}
__device__ __forceinline__ void ldmx4t(uint32_t* r, uint32_t addr) {
    asm volatile("ldmatrix.sync.aligned.m8n8.x4.trans.shared.b16 {%0,%1,%2,%3}, [%4];"
                 : "=r"(r[0]), "=r"(r[1]), "=r"(r[2]), "=r"(r[3]) : "r"(addr));
}
__device__ __forceinline__ void mma16816(float* c, const uint32_t* a,
                                         uint32_t b0, uint32_t b1) {
    asm volatile("mma.sync.aligned.m16n8k16.row.col.f32.bf16.bf16.f32 "
                 "{%0,%1,%2,%3}, {%4,%5,%6,%7}, {%8,%9}, {%0,%1,%2,%3};"
                 : "+f"(c[0]), "+f"(c[1]), "+f"(c[2]), "+f"(c[3])
                 : "r"(a[0]), "r"(a[1]), "r"(a[2]), "r"(a[3]), "r"(b0), "r"(b1));
}
#define CP16(dst, src) \
    asm volatile("cp.async.cg.shared.global [%0], [%1], 16;" :: "r"(dst), "l"(src))
#define CP_COMMIT() asm volatile("cp.async.commit_group;" ::: "memory")
#define CP_WAIT0()  asm volatile("cp.async.wait_group 0;" ::: "memory")
#define CP_WAIT1()  asm volatile("cp.async.wait_group 1;" ::: "memory")

// ---------------------------------------------------------------------------
__global__ __launch_bounds__(256)
void prep_kernel(const float* __restrict__ wq, const float* __restrict__ wkv,
                 const float* __restrict__ wproj, const float* __restrict__ w1,
                 const float* __restrict__ w2,
                 const float* __restrict__ bq, const float* __restrict__ bkv,
                 __nv_bfloat16* __restrict__ wh, float* __restrict__ bqkv)
{
    const int i = blockIdx.x * 256 + threadIdx.x;
    if (i < WTOTAL) {
        const float* src; int off;
        if      (i < WOFF_KV)   { src = wq;    off = i; }
        else if (i < WOFF_PROJ) { src = wkv;   off = i - WOFF_KV; }
        else if (i < WOFF_W1)   { src = wproj; off = i - WOFF_PROJ; }
        else if (i < WOFF_W2)   { src = w1;    off = i - WOFF_W1; }
        else                    { src = w2;    off = i - WOFF_W2; }
        wh[i] = __float2bfloat16(src[off]);
    }
    if (i < QKVO) bqkv[i] = (i < MIDD) ? bq[i] : bkv[i - MIDD];
}

__global__ __launch_bounds__(256)
void ln_kernel(const float* __restrict__ x, const float* __restrict__ g,
               const float* __restrict__ beta,
               __nv_bfloat16* __restrict__ oh, __nv_bfloat16* __restrict__ ol)
{
    const int b = blockIdx.y;
    const int n = blockIdx.x * 256 + threadIdx.x;
    const float* xp = x + (size_t)b * CC * NN + n;

    float sum = 0.f, sq = 0.f;
    #pragma unroll 4
    for (int c = 0; c < CC; c++) {
        float v = xp[(size_t)c * NN];
        sum += v; sq += v * v;
    }
    const float mean = sum * (1.f / CC);
    float var = sq * (1.f / CC) - mean * mean;
    var = var < 0.f ? 0.f : var;
    const float rstd = rsqrtf(var + 1e-5f);

    __nv_bfloat16* ph = oh + (size_t)b * CC * NN + n;
    __nv_bfloat16* pl = ol + (size_t)b * CC * NN + n;
    #pragma unroll 4
    for (int c = 0; c < CC; c++) {
        float v = (xp[(size_t)c * NN] - mean) * rstd * g[c] + beta[c];
        const __nv_bfloat16 h = __float2bfloat16(v);
        ph[(size_t)c * NN] = h;
        pl[(size_t)c * NN] = __float2bfloat16(v - __bfloat162float(h));
    }
}

// ---------------------------------------------------------------------------
// Pipelined HMMA GEMM (measured in the 784us run; unchanged).
// ---------------------------------------------------------------------------
#define GROW 272
#define BROW 144
#define ST_A_HI 0
#define ST_A_LO 17408
#define ST_B_HI 34816
#define ST_SIZE 44032
#define SM_GEMM_TOTAL (2 * ST_SIZE)   // 88064

template<int EPI>
__global__ __launch_bounds__(256, 2)
void mma_gemm(const __nv_bfloat16* __restrict__ Wh,
              const __nv_bfloat16* __restrict__ Ah, const __nv_bfloat16* __restrict__ Al,
              const float* __restrict__ bias, const float* __restrict__ res,
              void* __restrict__ out1, void* __restrict__ out2, int O, int K)
{
    extern __shared__ __align__(16) char smem[];
    const uint32_t sbase = smem_to_u32(smem);

    const int b   = blockIdx.z;
    const int n0  = blockIdx.x * 128;
    const int o0  = blockIdx.y * 64;
    const int tid = threadIdx.x;
    const int wid = tid >> 5;
    const int lane = tid & 31;
    const int wm = wid & 3;
    const int wn = wid >> 2;

    const __nv_bfloat16* Abh = Ah + (size_t)b * K * NN;
    const __nv_bfloat16* Abl = Al + (size_t)b * K * NN;

    float acc[2][4][4];
    #pragma unroll
    for (int i = 0; i < 2; i++)
        #pragma unroll
        for (int j = 0; j < 4; j++)
            #pragma unroll
            for (int e = 0; e < 4; e++) acc[i][j][e] = 0.f;

    const int a_kr = (lane & 7) + ((lane & 16) ? 8 : 0);
    const int a_mc = ((lane & 8) ? 8 : 0);
    const int b_row = wn * 32 + (lane & 7) + ((lane >> 4) & 1) * 8;
    const int b_kg  = (lane >> 3) & 1;

    const int nchunks = K >> 6;

    auto prefetch = [&](int chunk, int stage) {
        const uint32_t sbuf = sbase + stage * ST_SIZE;
        const int k0 = chunk << 6;
        #pragma unroll
        for (int r = 0; r < 4; r++) {
            const int u = tid + 256 * r;
            const int row = u >> 4, blk = u & 15;
            const uint32_t d = (uint32_t)(row * GROW + blk * 16);
            const size_t aidx = (size_t)(k0 + row) * NN + n0 + blk * 8;
            CP16(sbuf + ST_A_HI + d, Abh + aidx);
            CP16(sbuf + ST_A_LO + d, Abl + aidx);
        }
        #pragma unroll
        for (int r = 0; r < 2; r++) {
            const int u = tid + 256 * r;
            const int row = u >> 3, g = u & 7;
            const uint32_t d = (uint32_t)(row * BROW + g * 16);
            const size_t widx = (size_t)(o0 + row) * K + k0 + g * 8;
            CP16(sbuf + ST_B_HI + d, Wh + widx);
        }
    };

    prefetch(0, 0); CP_COMMIT();

    for (int chunk = 0; chunk < nchunks; chunk++) {
        const int cur = chunk & 1;
        if (chunk + 1 < nchunks) prefetch(chunk + 1, cur ^ 1);
        CP_COMMIT();                    // unconditional: empty group on tail
        CP_WAIT1();
        __syncthreads();

        const uint32_t sbuf = sbase + cur * ST_SIZE;
        #pragma unroll
        for (int ks = 0; ks < 4; ks++) {
            uint32_t bh[8];
            #pragma unroll
            for (int ng = 0; ng < 2; ng++) {
                const uint32_t boff =
                    (uint32_t)((b_row + ng * 16) * BROW + (ks * 2 + b_kg) * 16);
                ldmx4(&bh[ng * 4], sbuf + ST_B_HI + boff);
            }
            #pragma unroll
            for (int mf = 0; mf < 2; mf++) {
                const uint32_t aoff = (uint32_t)((ks * 16 + a_kr) * GROW
                                   + (wm * 32 + mf * 16 + a_mc) * 2);
                uint32_t ah[4], al[4];
                ldmx4t(ah, sbuf + ST_A_HI + aoff);
                ldmx4t(al, sbuf + ST_A_LO + aoff);
                #pragma unroll
                for (int nf = 0; nf < 4; nf++) {
                    const int bi = (nf >> 1) * 4 + (nf & 1) * 2;
                    mma16816(acc[mf][nf], ah, bh[bi], bh[bi + 1]);
                    mma16816(acc[mf][nf], al, bh[bi], bh[bi + 1]);
                }
            }
        }
        __syncthreads();
    }

    float* Cs = (float*)smem;  // [64 o][132 m]
    #pragma unroll
    for (int mf = 0; mf < 2; mf++) {
        const int m = wm * 32 + mf * 16 + (lane >> 2);
        #pragma unroll
        for (int nf = 0; nf < 4; nf++) {
            const int ol = wn * 32 + nf * 8 + (lane & 3) * 2;
            Cs[ ol      * 132 + m    ] = acc[mf][nf][0];
            Cs[(ol + 1) * 132 + m    ] = acc[mf][nf][1];
            Cs[ ol      * 132 + m + 8] = acc[mf][nf][2];
            Cs[(ol + 1) * 132 + m + 8] = acc[mf][nf][3];
        }
    }
    __syncthreads();

    #pragma unroll 4
    for (int i = 0; i < 32; i++) {
        const int idx = tid + 256 * i;
        const int ol = idx >> 7;
        const int m  = idx & 127;
        const int o  = o0 + ol;
        float v = Cs[ol * 132 + m] + bias[o];
        const size_t gidx = ((size_t)b * O + o) * NN + n0 + m;
        if (EPI == 1) {
            ((float*)out1)[gidx] = v + res[gidx];
        } else {
            if (EPI == 4) v = 0.5f * v * (1.f + erff(v * 0.7071067811865476f));
            const __nv_bfloat16 h = __float2bfloat16(v);
            ((__nv_bfloat16*)out1)[gidx] = h;
            ((__nv_bfloat16*)out2)[gidx] = __float2bfloat16(v - __bfloat162float(h));
        }
    }
}

// ---------------------------------------------------------------------------
// MMA flash attention, 64-key blocks, 2 CTAs/SM.
// QK: q(hi+lo) x K(hi); PV: P(hi) x V(hi). 16 kb iters; s[8][4].
// Unconditional commit per iter keeps WAIT1 group accounting exact.
// ---------------------------------------------------------------------------
#define KGROW 144                       // 64 keys * 2B + 16B pad
#define AST2_K 0
#define AST2_V 6912                     // 48 * 144
#define AST2_SIZE 13824
#define AT_BIAS_OFF 27648               // after 2 stages
#define AT_SMEM_TOTAL (27648 + 35 * 64 * 4)   // 36608
#define ATT_SCALE 0.14433756729740643f

__global__ __launch_bounds__(256, 2)
void attn_kernel(const __nv_bfloat16* __restrict__ QKVh,
                 const __nv_bfloat16* __restrict__ QKVl,
                 const float* __restrict__ rpb,
                 __nv_bfloat16* __restrict__ Oh, __nv_bfloat16* __restrict__ Ol)
{
    extern __shared__ __align__(16) char smem[];
    const uint32_t sb = smem_to_u32(smem);
    const int tid = threadIdx.x, lane = tid & 31, w = tid >> 5;
    const int qb = blockIdx.x, h = blockIdx.y, b = blockIdx.z;

    float* bias_s = (float*)(smem + AT_BIAS_OFF);
    for (int e = tid; e < 35 * 63; e += 256) {
        const int a = e / 63, dw = e % 63;
        bias_s[a * 64 + dw] = rpb[((size_t)((a + qb * 4) * 63 + dw)) * NHH + h];
    }

    const size_t qrow = (size_t)(b * QKVO + h * HDD) * NN;
    const size_t krow = (size_t)(b * QKVO + MIDD + h * HDD) * NN;
    const size_t vrow = (size_t)(b * QKVO + 2 * MIDD + h * HDD) * NN;

    // ---- stage Q: hi at sb+0, lo at sb+13056 ([48 d][128 q], 272B rows) ----
    {
        #pragma unroll
        for (int r = 0; r < 3; r++) {
            const int u = tid + 256 * r;           // 0..767
            const int row = u >> 4, blk = u & 15;  // row<48, blk<16
            const uint32_t d = (uint32_t)(row * GROW + blk * 16);
            const size_t qidx = qrow + (size_t)row * NN + qb * 128 + blk * 8;
            CP16(sb + d,         QKVh + qidx);
            CP16(sb + 13056 + d, QKVl + qidx);
        }
    }
    CP_COMMIT();
    CP_WAIT0();
    __syncthreads();

    // Q fragments -> registers
    uint32_t qfh[3][4], qfl[3][4];
    {
        const int q_dr = (lane & 7) + ((lane & 16) ? 8 : 0);
        const int q_mc = ((lane & 8) ? 8 : 0);
        #pragma unroll
        for (int ks = 0; ks < 3; ks++) {
            const uint32_t off = (uint32_t)((ks * 16 + q_dr) * GROW
                               + (w * 16 + q_mc) * 2);
            ldmx4t(qfh[ks], sb + off);
            ldmx4t(qfl[ks], sb + 13056 + off);
        }
    }
    __syncthreads();   // all warps done with Q smem before kb prefetches

    auto prefetchKV = [&](int kb, int stage) {
        const uint32_t sbuf = sb + stage * AST2_SIZE;
        #pragma unroll
        for (int r = 0; r < 3; r++) {
            const int u = tid + 256 * r;           // 0..767
            const int row2 = u >> 3, blk = u & 7;  // row2<96
            const int dr = (row2 < 48) ? row2 : row2 - 48;
            const uint32_t base = (row2 < 48) ? AST2_K : AST2_V;
            const size_t grow = (row2 < 48) ? krow : vrow;
            const uint32_t d = (uint32_t)(dr * KGROW + blk * 16);
            const size_t gidx = grow + (size_t)dr * NN + kb * 64 + blk * 8;
            CP16(sbuf + base + d, QKVh + gidx);
        }
    };

    prefetchKV(0, 0); CP_COMMIT();
    prefetchKV(1, 1); CP_COMMIT();

    float of[6][4];
    #pragma unroll
    for (int i = 0; i < 6; i++)
        #pragma unroll
        for (int e = 0; e < 4; e++) of[i][e] = 0.f;
    float mrow0 = -1e30f, mrow1 = -1e30f, lrow0 = 0.f, lrow1 = 0.f;

    const int trow0 = w * 16 + (lane >> 2);
    const int hn0 = trow0 >> 5, wn0 = trow0 & 31;
    const int trow1 = trow0 + 8;
    const int hn1 = trow1 >> 5, wn1 = trow1 & 31;

    const int b_dr = (lane & 7) + ((lane & 8) ? 8 : 0);
    const int b_kc = ((lane & 16) ? 8 : 0);
    const int v_dr = (lane & 7) + ((lane & 16) ? 8 : 0);
    const int v_kc = ((lane & 8) ? 8 : 0);

    for (int kb = 0; kb < 16; kb++) {
        const int cur = kb & 1;
        CP_WAIT1();
        __syncthreads();
        const uint32_t sbuf = sb + cur * AST2_SIZE;

        // S = Q K^T over 64 keys (8 nfrags)
        float s[8][4];
        #pragma unroll
        for (int i = 0; i < 8; i++)
            #pragma unroll
            for (int e = 0; e < 4; e++) s[i][e] = 0.f;

        #pragma unroll
        for (int ks = 0; ks < 3; ks++) {
            #pragma unroll
            for (int np = 0; np < 4; np++) {
                const uint32_t off = (uint32_t)((ks * 16 + b_dr) * KGROW
                                   + (np * 16 + b_kc) * 2);
                uint32_t kh4[4];
                ldmx4t(kh4, sbuf + AST2_K + off);
                mma16816(s[2*np],   qfh[ks], kh4[0], kh4[1]);
                mma16816(s[2*np],   qfl[ks], kh4[0], kh4[1]);
                mma16816(s[2*np+1], qfh[ks], kh4[2], kh4[3]);
                mma16816(s[2*np+1], qfl[ks], kh4[2], kh4[3]);
            }
        }

        // scale + bias + online softmax
        float mx0 = -1e30f, mx1 = -1e30f;
        #pragma unroll
        for (int nf = 0; nf < 8; nf++) {
            const int j0 = nf * 8 + (lane & 3) * 2;
            const int hm = (kb * 64 + j0) >> 5;
            const int wm = j0 & 31;
            const float* br0 = bias_s + (hn0 + 31 - hm) * 64 + (wn0 - wm + 31);
            const float* br1 = bias_s + (hn1 + 31 - hm) * 64 + (wn1 - wm + 31);
            s[nf][0] = s[nf][0] * ATT_SCALE + br0[0];
            s[nf][1] = s[nf][1] * ATT_SCALE + br0[-1];
            s[nf][2] = s[nf][2] * ATT_SCALE + br1[0];
            s[nf][3] = s[nf][3] * ATT_SCALE + br1[-1];
            mx0 = fmaxf(mx0, fmaxf(s[nf][0], s[nf][1]));
            mx1 = fmaxf(mx1, fmaxf(s[nf][2], s[nf][3]));
        }
        mx0 = fmaxf(mx0, __shfl_xor_sync(0xffffffffu, mx0, 1));
        mx0 = fmaxf(mx0, __shfl_xor_sync(0xffffffffu, mx0, 2));
        mx1 = fmaxf(mx1, __shfl_xor_sync(0xffffffffu, mx1, 1));
        mx1 = fmaxf(mx1, __shfl_xor_sync(0xffffffffu, mx1, 2));
        const float mn0 = fmaxf(mrow0, mx0), mn1 = fmaxf(mrow1, mx1);
        const float c0 = __expf(mrow0 - mn0), c1 = __expf(mrow1 - mn1);
        mrow0 = mn0; mrow1 = mn1;
        #pragma unroll
        for (int nf = 0; nf < 6; nf++) {
            of[nf][0] *= c0; of[nf][1] *= c0;
            of[nf][2] *= c1; of[nf][3] *= c1;
        }
        float sum0 = 0.f, sum1 = 0.f;
        #pragma unroll
        for (int nf = 0; nf < 8; nf++) {
            s[nf][0] = __expf(s[nf][0] - mn0); sum0 += s[nf][0];
            s[nf][1] = __expf(s[nf][1] - mn0); sum0 += s[nf][1];
            s[nf][2] = __expf(s[nf][2] - mn1); sum1 += s[nf][2];
            s[nf][3] = __expf(s[nf][3] - mn1); sum1 += s[nf][3];
        }
        sum0 += __shfl_xor_sync(0xffffffffu, sum0, 1);
        sum0 += __shfl_xor_sync(0xffffffffu, sum0, 2);
        sum1 += __shfl_xor_sync(0xffffffffu, sum1, 1);
        sum1 += __shfl_xor_sync(0xffffffffu, sum1, 2);
        lrow0 = lrow0 * c0 + sum0;
        lrow1 = lrow1 * c1 + sum1;

        // O += P V (P hi only, V hi only)
        #pragma unroll
        for (int ks = 0; ks < 4; ks++) {
            uint32_t ah[4];
            {
                const float f[8] = {s[2*ks][0],   s[2*ks][1],   s[2*ks][2],   s[2*ks][3],
                                    s[2*ks+1][0], s[2*ks+1][1], s[2*ks+1][2], s[2*ks+1][3]};
                #pragma unroll
                for (int i = 0; i < 4; i++) {
                    __nv_bfloat162 hh(__float2bfloat16(f[2*i]), __float2bfloat16(f[2*i+1]));
                    ah[i] = *(uint32_t*)&hh;
                }
            }
            #pragma unroll
            for (int np = 0; np < 3; np++) {
                const uint32_t off = (uint32_t)((np * 16 + v_dr) * KGROW
                                   + (ks * 16 + v_kc) * 2);
                uint32_t vh4[4];
                ldmx4(vh4, sbuf + AST2_V + off);
                mma16816(of[2*np],   ah, vh4[0], vh4[1]);
                mma16816(of[2*np+1], ah, vh4[2], vh4[3]);
            }
        }
        __syncthreads();
        if (kb + 2 < 16) prefetchKV(kb + 2, cur);
        CP_COMMIT();                    // unconditional: empty group on tail
    }

    const float inv0 = 1.f / lrow0, inv1 = 1.f / lrow1;
    float* Os = (float*)smem;   // [48 d][132]
    #pragma unroll
    for (int nf = 0; nf < 6; nf++) {
        const int d0 = nf * 8 + (lane & 3) * 2;
        const int t0 = w * 16 + (lane >> 2);
        Os[ d0      * 132 + t0    ] = of[nf][0] * inv0;
        Os[(d0 + 1) * 132 + t0    ] = of[nf][1] * inv0;
        Os[ d0      * 132 + t0 + 8] = of[nf][2] * inv1;
        Os[(d0 + 1) * 132 + t0 + 8] = of[nf][3] * inv1;
    }
    __syncthreads();
    const size_t orow = (size_t)(b * MIDD + h * HDD) * NN;
    #pragma unroll
    for (int i = 0; i < 24; i++) {
        const int u = tid + 256 * i;
        const int d = u >> 7, t = u & 127;
        const float v = Os[d * 132 + t];
        const size_t gidx = orow + (size_t)d * NN + qb * 128 + t;
        const __nv_bfloat16 hh = __float2bfloat16(v);
        Oh[gidx] = hh;
        Ol[gidx] = __float2bfloat16(v - __bfloat162float(hh));
    }
}

// ---------------------------------------------------------------------------
extern "C" void kernel_launch(void* const* d_in, const int* in_sizes, int n_in,
                              void* d_out, int out_size)
{
    const float* x     = (const float*)d_in[0];
    const float* rpb   = (const float*)d_in[1];
    const float* ln1_g = (const float*)d_in[3];
    const float* ln1_b = (const float*)d_in[4];
    const float* ln2_g = (const float*)d_in[5];
    const float* ln2_b = (const float*)d_in[6];
    const float* wq    = (const float*)d_in[7];
    const float* bq    = (const float*)d_in[8];
    const float* wkv   = (const float*)d_in[9];
    const float* bkv   = (const float*)d_in[10];
    const float* wproj = (const float*)d_in[11];
    const float* bproj = (const float*)d_in[12];
    const float* w1    = (const float*)d_in[13];
    const float* b1    = (const float*)d_in[14];
    const float* w2    = (const float*)d_in[15];
    const float* b2    = (const float*)d_in[16];
    float* out = (float*)d_out;

    __nv_bfloat16 *p_lnh, *p_lnl, *p_qkvh, *p_qkvl,
                  *p_aoh, *p_aol, *p_mh, *p_ml, *p_wh;
    float *p_y1, *p_bqkv;
    cudaGetSymbolAddress((void**)&p_lnh,  g_lnh);
    cudaGetSymbolAddress((void**)&p_lnl,  g_lnl);
    cudaGetSymbolAddress((void**)&p_qkvh, g_qkvh);
    cudaGetSymbolAddress((void**)&p_qkvl, g_qkvl);
    cudaGetSymbolAddress((void**)&p_aoh,  g_aoh);
    cudaGetSymbolAddress((void**)&p_aol,  g_aol);
    cudaGetSymbolAddress((void**)&p_mh,   g_mh);
    cudaGetSymbolAddress((void**)&p_ml,   g_ml);
    cudaGetSymbolAddress((void**)&p_y1,   g_y1);
    cudaGetSymbolAddress((void**)&p_wh,   g_wh);
    cudaGetSymbolAddress((void**)&p_bqkv, g_bqkv);

    cudaFuncSetAttribute(mma_gemm<1>, cudaFuncAttributeMaxDynamicSharedMemorySize, SM_GEMM_TOTAL);
    cudaFuncSetAttribute(mma_gemm<3>, cudaFuncAttributeMaxDynamicSharedMemorySize, SM_GEMM_TOTAL);
    cudaFuncSetAttribute(mma_gemm<4>, cudaFuncAttributeMaxDynamicSharedMemorySize, SM_GEMM_TOTAL);
    cudaFuncSetAttribute(attn_kernel, cudaFuncAttributeMaxDynamicSharedMemorySize, AT_SMEM_TOTAL);

    prep_kernel<<<(WTOTAL + 255) / 256, 256>>>(wq, wkv, wproj, w1, w2, bq, bkv,
                                               p_wh, p_bqkv);

    const dim3 lnGrid(NN / 256, BB);

    ln_kernel<<<lnGrid, 256>>>(x, ln1_g, ln1_b, p_lnh, p_lnl);
    mma_gemm<3><<<dim3(NN/128, QKVO/64, BB), 256, SM_GEMM_TOTAL>>>(
        p_wh + WOFF_Q, p_lnh, p_lnl, p_bqkv, nullptr, p_qkvh, p_qkvl, QKVO, CC);
    attn_kernel<<<dim3(NN/128, NHH, BB), 256, AT_SMEM_TOTAL>>>(
        p_qkvh, p_qkvl, rpb, p_aoh, p_aol);
    mma_gemm<1><<<dim3(NN/128, CC/64, BB), 256, SM_GEMM_TOTAL>>>(
        p_wh + WOFF_PROJ, p_aoh, p_aol, bproj, x, p_y1, nullptr, CC, MIDD);
    ln_kernel<<<lnGrid, 256>>>(p_y1, ln2_g, ln2_b, p_lnh, p_lnl);
    mma_gemm<4><<<dim3(NN/128, HIDD/64, BB), 256, SM_GEMM_TOTAL>>>(
        p_wh + WOFF_W1, p_lnh, p_lnl, b1, nullptr, p_mh, p_ml, HIDD, CC);
    mma_gemm<1><<<dim3(NN/128, CC/64, BB), 256, SM_GEMM_TOTAL>>>(
        p_wh + WOFF_W2, p_mh, p_ml, b2, p_y1, out, nullptr, CC, HIDD);
}